// round 7
// baseline (speedup 1.0000x reference)
#include <cuda_runtime.h>
#include <cstdint>
#include <cstdio>

// Problem constants
#define BB   64      // batch
#define TT   256     // seq len
#define DIN  512     // input dim (layer 0)
#define HH   1024    // hidden
#define PP   256     // proj
#define G4H  4096    // 4*H

// ---------------------------------------------------------------------------
// Scratch (__device__ globals; allocation is forbidden)
// ---------------------------------------------------------------------------
__device__ float g_xg[(size_t)TT * BB * G4H];   // [T,B,4H] gate pre-activations (268 MB)
__device__ float g_hpA[TT * BB * PP];           // [T,B,P]
__device__ float g_hpB[TT * BB * PP];           // [T,B,P]
__device__ float g_h[BB * HH];                  // [B,H] full hidden, per step
__device__ unsigned g_cnt = 0;
__device__ volatile unsigned g_gen = 0;

// ---------------------------------------------------------------------------
// Grid barrier (all blocks co-resident: 128 blocks, 1/SM on 148 SMs)
// ---------------------------------------------------------------------------
__device__ __forceinline__ void grid_barrier() {
    __syncthreads();
    __threadfence();
    if (threadIdx.x == 0) {
        unsigned mygen = g_gen;
        if (atomicAdd(&g_cnt, 1u) == gridDim.x - 1u) {
            g_cnt = 0;
            __threadfence();
            g_gen = mygen + 1u;
        } else {
            while (g_gen == mygen) { }
            __threadfence();
        }
    }
    __syncthreads();
}

// ---------------------------------------------------------------------------
// Input-projection GEMM:  C[row(m)][n] = sum_k A[m][k]*W[n][k] + b1[n] + b2[n]
// A: [M,K] row-major, W: [4096,K] row-major. N = 4096 fixed, M = 16384.
// mode 0: A rows are (b,t) (m = b*256+t), output row = t*64+b  (layer 0, x input)
// mode 1: identity row map (layers 1..3, hp input already [T,B,P])
// Tiling: 128x128x8, 256 threads, 8x8 per-thread tile.
// ---------------------------------------------------------------------------
__global__ __launch_bounds__(256, 2) void gemm_xg_kernel(
    const float* __restrict__ A, const float* __restrict__ W,
    const float* __restrict__ b1, const float* __restrict__ b2,
    float* __restrict__ C, int K, int mode)
{
    __shared__ float As[8][132];
    __shared__ float Ws[8][132];

    const int tid = threadIdx.x;
    const int n0 = blockIdx.x * 128;
    const int m0 = blockIdx.y * 128;
    const int tx = tid & 15;        // n tile
    const int ty = tid >> 4;        // m tile
    const int lr = tid >> 1;        // load row 0..127
    const int lc = (tid & 1) * 4;   // load col 0 or 4

    float bsum[8];
#pragma unroll
    for (int j = 0; j < 8; j++) {
        int n = n0 + tx * 8 + j;
        bsum[j] = b1[n] + b2[n];
    }

    float acc[8][8];
#pragma unroll
    for (int i = 0; i < 8; i++)
#pragma unroll
        for (int j = 0; j < 8; j++) acc[i][j] = 0.f;

    for (int kk = 0; kk < K; kk += 8) {
        float4 av = *(const float4*)&A[(size_t)(m0 + lr) * K + kk + lc];
        float4 wv = *(const float4*)&W[(size_t)(n0 + lr) * K + kk + lc];
        __syncthreads();
        As[lc + 0][lr] = av.x; As[lc + 1][lr] = av.y;
        As[lc + 2][lr] = av.z; As[lc + 3][lr] = av.w;
        Ws[lc + 0][lr] = wv.x; Ws[lc + 1][lr] = wv.y;
        Ws[lc + 2][lr] = wv.z; Ws[lc + 3][lr] = wv.w;
        __syncthreads();
#pragma unroll
        for (int k = 0; k < 8; k++) {
            float4 a0 = *(const float4*)&As[k][ty * 8];
            float4 a1 = *(const float4*)&As[k][ty * 8 + 4];
            float4 w0 = *(const float4*)&Ws[k][tx * 8];
            float4 w1 = *(const float4*)&Ws[k][tx * 8 + 4];
            float ar[8] = {a0.x, a0.y, a0.z, a0.w, a1.x, a1.y, a1.z, a1.w};
            float wr[8] = {w0.x, w0.y, w0.z, w0.w, w1.x, w1.y, w1.z, w1.w};
#pragma unroll
            for (int i = 0; i < 8; i++)
#pragma unroll
                for (int j = 0; j < 8; j++)
                    acc[i][j] = fmaf(ar[i], wr[j], acc[i][j]);
        }
    }

#pragma unroll
    for (int i = 0; i < 8; i++) {
        int m = m0 + ty * 8 + i;
        int row = (mode == 0) ? (((m & 255) << 6) + (m >> 8)) : m;
        float* cp = C + (size_t)row * G4H + n0 + tx * 8;
        float4 o0 = make_float4(acc[i][0] + bsum[0], acc[i][1] + bsum[1],
                                acc[i][2] + bsum[2], acc[i][3] + bsum[3]);
        float4 o1 = make_float4(acc[i][4] + bsum[4], acc[i][5] + bsum[5],
                                acc[i][6] + bsum[6], acc[i][7] + bsum[7]);
        *(float4*)(cp)     = o0;
        *(float4*)(cp + 4) = o1;
    }
}

// ---------------------------------------------------------------------------
// Persistent LSTM scan for one layer.
// 128 blocks x 512 threads, 1 block/SM.
// Block j:
//   Phase A: gate columns k in [j*8, j*8+8), all 64 batches, all 4 gates.
//            c state lives in registers (1 cell per thread). Writes h -> g_h.
//   Phase B: projection tile p in [ (j&15)*16 , +16 ), b in [ (j>>4)*8, +8 ).
//            Writes hp_out[t].
// W_hh slice (32KB) and W_hr slice (64KB) persistent in SMEM for all T steps.
// ---------------------------------------------------------------------------
#define SCAN_SMEM ((32 * 256 + 16 * 1028 + 64 * 260) * 4)

__global__ __launch_bounds__(512, 1) void lstm_scan_kernel(
    const float* __restrict__ xg,    // [T*B, 4096]
    const float* __restrict__ W_hh,  // [4096, 256]
    const float* __restrict__ W_hr,  // [256, 1024]
    float* __restrict__ hp_out,      // [T*B, 256]
    float* __restrict__ h_buf)       // [64, 1024]
{
    extern __shared__ float smem[];
    float* sWhh  = smem;                    // [32][256]   gate rows: r = g*8+kl
    float* sWhr  = smem + 32 * 256;         // [16][1028]
    float* stage = sWhr + 16 * 1028;        // union: hp_s [64][260] / sh [8][1028]

    const int tid = threadIdx.x;
    const int j   = blockIdx.x;
    const int k0  = j * 8;
    const int p0  = (j & 15) * 16;
    const int b0  = (j >> 4) * 8;

    // Load persistent weight slices
    for (int idx = tid; idx < 32 * 64; idx += 512) {        // W_hh: 32 rows x 64 f4
        int r = idx >> 6, c4 = idx & 63;
        int g = r >> 3, kl = r & 7;
        float4 v = *(const float4*)&W_hh[(size_t)(g * 1024 + k0 + kl) * 256 + c4 * 4];
        *(float4*)&sWhh[r * 256 + c4 * 4] = v;
    }
    for (int idx = tid; idx < 16 * 256; idx += 512) {       // W_hr: 16 rows x 256 f4
        int r = idx >> 8, c4 = idx & 255;
        float4 v = *(const float4*)&W_hr[(size_t)(p0 + r) * 1024 + c4 * 4];
        *(float4*)&sWhr[r * 1028 + c4 * 4] = v;
    }

    // Phase A roles: thread owns gate-column k0+kl, batch b. c in register.
    const int kl = tid >> 6;   // 0..7
    const int b  = tid & 63;   // 0..63
    float c_reg = 0.f;

    // Phase B roles: 4 threads per (bb,pp) dot, quarter each.
    const int cell = tid >> 2;          // 0..127
    const int q    = tid & 3;
    const int pb   = cell >> 4;         // 0..7  (local batch)
    const int ppp  = cell & 15;         // 0..15 (local proj col)

    __syncthreads();

    for (int t = 0; t < TT; t++) {
        // ---- stage hp(t-1) into SMEM [64][260] ----
        if (t == 0) {
            for (int idx = tid; idx < 64 * 64; idx += 512) {
                int r = idx >> 6, c4 = idx & 63;
                *(float4*)&stage[r * 260 + c4 * 4] = make_float4(0.f, 0.f, 0.f, 0.f);
            }
        } else {
            const float* src = hp_out + (size_t)(t - 1) * BB * PP;
            for (int idx = tid; idx < 64 * 64; idx += 512) {
                int r = idx >> 6, c4 = idx & 63;
                float4 v = __ldcg((const float4*)&src[r * 256 + c4 * 4]);
                *(float4*)&stage[r * 260 + c4 * 4] = v;
            }
        }
        __syncthreads();

        // ---- Phase A: 4 gate dots of length 256 ----
        float a0 = 0.f, a1 = 0.f, a2 = 0.f, a3 = 0.f;
        {
            const float* hrow = &stage[b * 260];
            const float* wr0 = &sWhh[(0 * 8 + kl) * 256];
            const float* wr1 = &sWhh[(1 * 8 + kl) * 256];
            const float* wr2 = &sWhh[(2 * 8 + kl) * 256];
            const float* wr3 = &sWhh[(3 * 8 + kl) * 256];
#pragma unroll 4
            for (int p4 = 0; p4 < 64; p4++) {
                float4 hv = *(const float4*)&hrow[p4 * 4];
                float4 w0 = *(const float4*)&wr0[p4 * 4];
                float4 w1 = *(const float4*)&wr1[p4 * 4];
                float4 w2 = *(const float4*)&wr2[p4 * 4];
                float4 w3 = *(const float4*)&wr3[p4 * 4];
                a0 = fmaf(hv.x, w0.x, a0); a1 = fmaf(hv.x, w1.x, a1);
                a2 = fmaf(hv.x, w2.x, a2); a3 = fmaf(hv.x, w3.x, a3);
                a0 = fmaf(hv.y, w0.y, a0); a1 = fmaf(hv.y, w1.y, a1);
                a2 = fmaf(hv.y, w2.y, a2); a3 = fmaf(hv.y, w3.y, a3);
                a0 = fmaf(hv.z, w0.z, a0); a1 = fmaf(hv.z, w1.z, a1);
                a2 = fmaf(hv.z, w2.z, a2); a3 = fmaf(hv.z, w3.z, a3);
                a0 = fmaf(hv.w, w0.w, a0); a1 = fmaf(hv.w, w1.w, a1);
                a2 = fmaf(hv.w, w2.w, a2); a3 = fmaf(hv.w, w3.w, a3);
            }
        }
        // gates + cell update (c in register)
        {
            const float* xr = xg + ((size_t)t * BB + b) * G4H + k0 + kl;
            float gi = a0 + xr[0];
            float gf = a1 + xr[1024];
            float gg = a2 + xr[2048];
            float go = a3 + xr[3072];
            gi = 1.f / (1.f + expf(-gi));
            gf = 1.f / (1.f + expf(-gf));
            gg = tanhf(gg);
            go = 1.f / (1.f + expf(-go));
            c_reg = gf * c_reg + gi * gg;
            float hv = go * tanhf(c_reg);
            __stcg(&h_buf[b * HH + k0 + kl], hv);
        }
        grid_barrier();

        // ---- Phase B: projection hp[t] = h @ W_hr^T (tile: 8 b x 16 p) ----
        {
            float* sh = stage;   // [8][1028]
            for (int idx = tid; idx < 8 * 256; idx += 512) {
                int r = idx >> 8, c4 = idx & 255;
                float4 v = __ldcg((const float4*)&h_buf[(size_t)(b0 + r) * HH + c4 * 4]);
                *(float4*)&sh[r * 1028 + c4 * 4] = v;
            }
            __syncthreads();

            const float* hr = &sh[pb * 1028];
            const float* wr = &sWhr[ppp * 1028];
            float s = 0.f;
#pragma unroll 4
            for (int i = 0; i < 64; i++) {
                int e = i * 16 + q * 4;   // interleaved quarters (bank-friendly)
                float4 hv = *(const float4*)&hr[e];
                float4 wv = *(const float4*)&wr[e];
                s = fmaf(hv.x, wv.x, s);
                s = fmaf(hv.y, wv.y, s);
                s = fmaf(hv.z, wv.z, s);
                s = fmaf(hv.w, wv.w, s);
            }
            s += __shfl_xor_sync(0xffffffffu, s, 1);
            s += __shfl_xor_sync(0xffffffffu, s, 2);
            if (q == 0)
                __stcg(&hp_out[((size_t)t * BB + (b0 + pb)) * PP + p0 + ppp], s);
        }
        grid_barrier();
    }
}

// ---------------------------------------------------------------------------
// Launch
// ---------------------------------------------------------------------------
extern "C" void kernel_launch(void* const* d_in, const int* in_sizes, int n_in,
                              void* d_out, int out_size)
{
    const float* x     = (const float*)d_in[0];
    const float* W_ih0 = (const float*)d_in[1];
    const float* W_hh0 = (const float*)d_in[2];
    const float* b_ih0 = (const float*)d_in[3];
    const float* b_hh0 = (const float*)d_in[4];
    const float* W_hr0 = (const float*)d_in[5];
    const float* W_ihs = (const float*)d_in[6];
    const float* W_hhs = (const float*)d_in[7];
    const float* b_ihs = (const float*)d_in[8];
    const float* b_hhs = (const float*)d_in[9];
    const float* W_hrs = (const float*)d_in[10];

    float *xg, *hpA, *hpB, *hb;
    cudaGetSymbolAddress((void**)&xg,  g_xg);
    cudaGetSymbolAddress((void**)&hpA, g_hpA);
    cudaGetSymbolAddress((void**)&hpB, g_hpB);
    cudaGetSymbolAddress((void**)&hb,  g_h);

    cudaFuncSetAttribute(lstm_scan_kernel,
                         cudaFuncAttributeMaxDynamicSharedMemorySize, SCAN_SMEM);

    dim3 ggrid(32, 128);   // N/128, M/128

    // layer 0
    gemm_xg_kernel<<<ggrid, 256>>>(x, W_ih0, b_ih0, b_hh0, xg, DIN, 0);
    lstm_scan_kernel<<<128, 512, SCAN_SMEM>>>(xg, W_hh0, W_hr0, hpA, hb);

    // layers 1..3
    float* cur = hpA;
    float* nxt = hpB;
    for (int l = 0; l < 3; l++) {
        gemm_xg_kernel<<<ggrid, 256>>>(cur,
                                       W_ihs + (size_t)l * G4H * PP,
                                       b_ihs + (size_t)l * G4H,
                                       b_hhs + (size_t)l * G4H,
                                       xg, PP, 1);
        lstm_scan_kernel<<<128, 512, SCAN_SMEM>>>(xg,
                                                  W_hhs + (size_t)l * G4H * PP,
                                                  W_hrs + (size_t)l * PP * HH,
                                                  nxt, hb);
        float* tmp = cur; cur = nxt; nxt = tmp;
    }

    // output = last timestep of final layer: rows [255*64 .. 255*64+63] of [T*B, P]
    cudaMemcpyAsync(d_out, cur + (size_t)(TT - 1) * BB * PP,
                    (size_t)BB * PP * sizeof(float),
                    cudaMemcpyDeviceToDevice);
    (void)in_sizes; (void)n_in; (void)out_size;
}

// round 9
// speedup vs baseline: 1.0808x; 1.0808x over previous
#include <cuda_runtime.h>
#include <cuda_bf16.h>
#include <cstdint>

// Problem constants
#define BB   64      // batch
#define TT   256     // seq len
#define DIN  512     // input dim (layer 0)
#define HH   1024    // hidden
#define PP   256     // proj
#define G4H  4096    // 4*H
#define MROWS (TT*BB)  // 16384 GEMM rows

// ---------------------------------------------------------------------------
// Scratch (__device__ globals; allocation is forbidden)
// ---------------------------------------------------------------------------
__device__ float g_xg[(size_t)MROWS * G4H];                 // [T*B, 4H]
__device__ float g_hpA[(size_t)MROWS * PP];
__device__ float g_hpB[(size_t)MROWS * PP];
__device__ float g_h[BB * HH];
__device__ __nv_bfloat16 g_Abf[(size_t)MROWS * (3 * DIN)];  // A' split-bf16 (K3 max 1536)
__device__ __nv_bfloat16 g_Wbf[(size_t)G4H * (3 * DIN)];    // W' split-bf16
__device__ unsigned g_cnt = 0;
__device__ volatile unsigned g_gen = 0;

// ---------------------------------------------------------------------------
// Helpers
// ---------------------------------------------------------------------------
__device__ __forceinline__ uint32_t smem_u32(const void* p) {
    uint32_t a;
    asm("{ .reg .u64 t; cvta.to.shared.u64 t, %1; cvt.u32.u64 %0, t; }" : "=r"(a) : "l"(p));
    return a;
}
__device__ __forceinline__ void cp_async16(uint32_t dst, const void* src) {
    asm volatile("cp.async.cg.shared.global [%0], [%1], 16;" :: "r"(dst), "l"(src));
}
__device__ __forceinline__ void ldm_x4(uint32_t addr, uint32_t& r0, uint32_t& r1,
                                       uint32_t& r2, uint32_t& r3) {
    asm volatile("ldmatrix.sync.aligned.m8n8.x4.shared.b16 {%0,%1,%2,%3}, [%4];"
                 : "=r"(r0), "=r"(r1), "=r"(r2), "=r"(r3) : "r"(addr));
}
__device__ __forceinline__ void mma16816(float* d, const uint32_t* a,
                                         uint32_t b0, uint32_t b1) {
    asm volatile(
        "mma.sync.aligned.m16n8k16.row.col.f32.bf16.bf16.f32 "
        "{%0,%1,%2,%3}, {%4,%5,%6,%7}, {%8,%9}, {%0,%1,%2,%3};"
        : "+f"(d[0]), "+f"(d[1]), "+f"(d[2]), "+f"(d[3])
        : "r"(a[0]), "r"(a[1]), "r"(a[2]), "r"(a[3]), "r"(b0), "r"(b1));
}

// ---------------------------------------------------------------------------
// Grid barrier (scan kernel; all 128 blocks co-resident, 1/SM)
// ---------------------------------------------------------------------------
__device__ __forceinline__ void grid_barrier() {
    __syncthreads();
    __threadfence();
    if (threadIdx.x == 0) {
        unsigned mygen = g_gen;
        if (atomicAdd(&g_cnt, 1u) == gridDim.x - 1u) {
            g_cnt = 0;
            __threadfence();
            g_gen = mygen + 1u;
        } else {
            while (g_gen == mygen) { }
            __threadfence();
        }
    }
    __syncthreads();
}

// ---------------------------------------------------------------------------
// Conversion: fp32 -> split bf16 (hi + lo), 3K-column layouts.
// A': cols [0,K)=hi, [K,2K)=hi, [2K,3K)=lo
// W': cols [0,K)=hi, [K,2K)=lo, [2K,3K)=hi
// => Ahi*Whi + Ahi*Wlo + Alo*Whi ~= A*W (residual ~2^-16 relative)
// ---------------------------------------------------------------------------
__global__ void conv_A_kernel(const float* __restrict__ in, __nv_bfloat16* __restrict__ out,
                              int K, int remap) {
    int idx = blockIdx.x * 256 + threadIdx.x;
    if (idx >= MROWS * K) return;
    int m = idx / K;
    int k = idx - m * K;
    float a = in[idx];
    int r = remap ? (((m & 255) << 6) | (m >> 8)) : m;   // (b,t) -> row t*64+b
    __nv_bfloat16 hi = __float2bfloat16(a);
    __nv_bfloat16 lo = __float2bfloat16(a - __bfloat162float(hi));
    size_t base = (size_t)r * (3 * K);
    out[base + k] = hi;
    out[base + K + k] = hi;
    out[base + 2 * K + k] = lo;
}

__global__ void conv_W_kernel(const float* __restrict__ in, __nv_bfloat16* __restrict__ out,
                              int K) {
    int idx = blockIdx.x * 256 + threadIdx.x;
    if (idx >= G4H * K) return;
    int n = idx / K;
    int k = idx - n * K;
    float a = in[idx];
    __nv_bfloat16 hi = __float2bfloat16(a);
    __nv_bfloat16 lo = __float2bfloat16(a - __bfloat162float(hi));
    size_t base = (size_t)n * (3 * K);
    out[base + k] = hi;
    out[base + K + k] = lo;
    out[base + 2 * K + k] = hi;
}

// ---------------------------------------------------------------------------
// Tensor-core GEMM via mma.sync (bf16, fp32 accum):
//   C[m][n] = sum_k A'[m][k] * W'[n][k] + b1[n] + b2[n]
// CTA tile 128(M)x128(N), K-chunk 32, double-buffered cp.async.
// 8 warps: 2(M) x 4(N), warp tile 64x32.
// SMEM tiles padded to 40 bf16/row (80B) -> conflict-free ldmatrix.
// ---------------------------------------------------------------------------
#define LDS_ROW 40
#define TILE_BYTES (128 * LDS_ROW * 2)

__global__ __launch_bounds__(256) void gemm_mma_kernel(
    const __nv_bfloat16* __restrict__ A,
    const __nv_bfloat16* __restrict__ W,
    const float* __restrict__ b1, const float* __restrict__ b2,
    float* __restrict__ C, int K3)
{
    __shared__ alignas(16) __nv_bfloat16 sA[2][128][LDS_ROW];
    __shared__ alignas(16) __nv_bfloat16 sB[2][128][LDS_ROW];

    const int tid  = threadIdx.x;
    const int wid  = tid >> 5;
    const int lane = tid & 31;
    const int m0 = blockIdx.y * 128;
    const int n0 = blockIdx.x * 128;
    const int wm = (wid >> 2) * 64;   // warp M offset (0 or 64)
    const int wn = (wid & 3) * 32;    // warp N offset

    const uint32_t sA_u = smem_u32(sA);
    const uint32_t sB_u = smem_u32(sB);

    // loader: 512 x 16B segments per tile, 2 per thread
    const int lrow0 = tid >> 1;                 // seg0: row = tid/2... use seg = i*256+tid
    (void)lrow0;

    float acc[4][4][4];
#pragma unroll
    for (int mi = 0; mi < 4; mi++)
#pragma unroll
        for (int nj = 0; nj < 4; nj++)
#pragma unroll
            for (int e = 0; e < 4; e++) acc[mi][nj][e] = 0.f;

    const int nchunks = K3 >> 5;

    // ldmatrix source addresses (within a buffer, byte offsets)
    const uint32_t a_off = (uint32_t)((wm + (lane & 15)) * LDS_ROW + ((lane >> 4) * 8)) * 2;
    const uint32_t b_off = (uint32_t)((wn + ((lane >> 3) & 1) * 8 + (lane & 7)) * LDS_ROW
                                      + ((lane >> 4) * 8)) * 2;

    // prefetch chunk 0
    {
        const __nv_bfloat16* Ag = A + (size_t)m0 * K3;
        const __nv_bfloat16* Wg = W + (size_t)n0 * K3;
#pragma unroll
        for (int i = 0; i < 2; i++) {
            int seg = i * 256 + tid;
            int row = seg >> 2, s = seg & 3;
            uint32_t off = (uint32_t)(row * LDS_ROW + s * 8) * 2;
            cp_async16(sA_u + off, Ag + (size_t)row * K3 + s * 8);
            cp_async16(sB_u + off, Wg + (size_t)row * K3 + s * 8);
        }
        asm volatile("cp.async.commit_group;" ::: "memory");
    }

    for (int c = 0; c < nchunks; c++) {
        const int buf = c & 1;
        if (c + 1 < nchunks) {
            const int nb = (c + 1) & 1;
            const __nv_bfloat16* Ag = A + (size_t)m0 * K3 + (c + 1) * 32;
            const __nv_bfloat16* Wg = W + (size_t)n0 * K3 + (c + 1) * 32;
#pragma unroll
            for (int i = 0; i < 2; i++) {
                int seg = i * 256 + tid;
                int row = seg >> 2, s = seg & 3;
                uint32_t off = (uint32_t)(nb * TILE_BYTES + (row * LDS_ROW + s * 8) * 2);
                cp_async16(sA_u + off, Ag + (size_t)row * K3 + s * 8);
                cp_async16(sB_u + off, Wg + (size_t)row * K3 + s * 8);
            }
            asm volatile("cp.async.commit_group;" ::: "memory");
            asm volatile("cp.async.wait_group 1;" ::: "memory");
        } else {
            asm volatile("cp.async.wait_group 0;" ::: "memory");
        }
        __syncthreads();

        const uint32_t abase = sA_u + buf * TILE_BYTES;
        const uint32_t bbase = sB_u + buf * TILE_BYTES;
#pragma unroll
        for (int ks = 0; ks < 2; ks++) {
            const uint32_t koff = (uint32_t)(ks * 16 * 2);
            uint32_t a[4][4];
#pragma unroll
            for (int mi = 0; mi < 4; mi++)
                ldm_x4(abase + a_off + koff + (uint32_t)(mi * 16 * LDS_ROW * 2),
                       a[mi][0], a[mi][1], a[mi][2], a[mi][3]);
            uint32_t bfrag[4][2];
#pragma unroll
            for (int g = 0; g < 2; g++) {
                uint32_t r0, r1, r2, r3;
                ldm_x4(bbase + b_off + koff + (uint32_t)(g * 16 * LDS_ROW * 2),
                       r0, r1, r2, r3);
                bfrag[g * 2 + 0][0] = r0; bfrag[g * 2 + 0][1] = r2;
                bfrag[g * 2 + 1][0] = r1; bfrag[g * 2 + 1][1] = r3;
            }
#pragma unroll
            for (int mi = 0; mi < 4; mi++)
#pragma unroll
                for (int nj = 0; nj < 4; nj++)
                    mma16816(acc[mi][nj], a[mi], bfrag[nj][0], bfrag[nj][1]);
        }
        __syncthreads();
    }

    // Epilogue: bias + store (thread holds C[m=r+{0,8}][n=c2..c2+1] per frag)
    float2 bs[4];
#pragma unroll
    for (int nj = 0; nj < 4; nj++) {
        int n = n0 + wn + nj * 8 + (lane & 3) * 2;
        bs[nj].x = b1[n] + b2[n];
        bs[nj].y = b1[n + 1] + b2[n + 1];
    }
#pragma unroll
    for (int mi = 0; mi < 4; mi++) {
        int mrow = m0 + wm + mi * 16 + (lane >> 2);
#pragma unroll
        for (int nj = 0; nj < 4; nj++) {
            int n = n0 + wn + nj * 8 + (lane & 3) * 2;
            float2 v0 = make_float2(acc[mi][nj][0] + bs[nj].x, acc[mi][nj][1] + bs[nj].y);
            float2 v1 = make_float2(acc[mi][nj][2] + bs[nj].x, acc[mi][nj][3] + bs[nj].y);
            *(float2*)&C[(size_t)mrow * G4H + n]       = v0;
            *(float2*)&C[(size_t)(mrow + 8) * G4H + n] = v1;
        }
    }
}

// ---------------------------------------------------------------------------
// Persistent LSTM scan for one layer (unchanged from passing R7 kernel).
// 128 blocks x 512 threads, 1 block/SM.
// ---------------------------------------------------------------------------
#define SCAN_SMEM ((32 * 256 + 16 * 1028 + 64 * 260) * 4)

__global__ __launch_bounds__(512, 1) void lstm_scan_kernel(
    const float* __restrict__ xg,    // [T*B, 4096]
    const float* __restrict__ W_hh,  // [4096, 256]
    const float* __restrict__ W_hr,  // [256, 1024]
    float* __restrict__ hp_out,      // [T*B, 256]
    float* __restrict__ h_buf)       // [64, 1024]
{
    extern __shared__ float smem[];
    float* sWhh  = smem;                    // [32][256]
    float* sWhr  = smem + 32 * 256;         // [16][1028]
    float* stage = sWhr + 16 * 1028;        // union: hp_s [64][260] / sh [8][1028]

    const int tid = threadIdx.x;
    const int j   = blockIdx.x;
    const int k0  = j * 8;
    const int p0  = (j & 15) * 16;
    const int b0  = (j >> 4) * 8;

    for (int idx = tid; idx < 32 * 64; idx += 512) {
        int r = idx >> 6, c4 = idx & 63;
        int g = r >> 3, kl = r & 7;
        float4 v = *(const float4*)&W_hh[(size_t)(g * 1024 + k0 + kl) * 256 + c4 * 4];
        *(float4*)&sWhh[r * 256 + c4 * 4] = v;
    }
    for (int idx = tid; idx < 16 * 256; idx += 512) {
        int r = idx >> 8, c4 = idx & 255;
        float4 v = *(const float4*)&W_hr[(size_t)(p0 + r) * 1024 + c4 * 4];
        *(float4*)&sWhr[r * 1028 + c4 * 4] = v;
    }

    const int kl = tid >> 6;
    const int b  = tid & 63;
    float c_reg = 0.f;

    const int cell = tid >> 2;
    const int q    = tid & 3;
    const int pb   = cell >> 4;
    const int ppp  = cell & 15;

    __syncthreads();

    for (int t = 0; t < TT; t++) {
        if (t == 0) {
            for (int idx = tid; idx < 64 * 64; idx += 512) {
                int r = idx >> 6, c4 = idx & 63;
                *(float4*)&stage[r * 260 + c4 * 4] = make_float4(0.f, 0.f, 0.f, 0.f);
            }
        } else {
            const float* src = hp_out + (size_t)(t - 1) * BB * PP;
            for (int idx = tid; idx < 64 * 64; idx += 512) {
                int r = idx >> 6, c4 = idx & 63;
                float4 v = __ldcg((const float4*)&src[r * 256 + c4 * 4]);
                *(float4*)&stage[r * 260 + c4 * 4] = v;
            }
        }
        __syncthreads();

        float a0 = 0.f, a1 = 0.f, a2 = 0.f, a3 = 0.f;
        {
            const float* hrow = &stage[b * 260];
            const float* wr0 = &sWhh[(0 * 8 + kl) * 256];
            const float* wr1 = &sWhh[(1 * 8 + kl) * 256];
            const float* wr2 = &sWhh[(2 * 8 + kl) * 256];
            const float* wr3 = &sWhh[(3 * 8 + kl) * 256];
#pragma unroll 4
            for (int p4 = 0; p4 < 64; p4++) {
                float4 hv = *(const float4*)&hrow[p4 * 4];
                float4 w0 = *(const float4*)&wr0[p4 * 4];
                float4 w1 = *(const float4*)&wr1[p4 * 4];
                float4 w2 = *(const float4*)&wr2[p4 * 4];
                float4 w3 = *(const float4*)&wr3[p4 * 4];
                a0 = fmaf(hv.x, w0.x, a0); a1 = fmaf(hv.x, w1.x, a1);
                a2 = fmaf(hv.x, w2.x, a2); a3 = fmaf(hv.x, w3.x, a3);
                a0 = fmaf(hv.y, w0.y, a0); a1 = fmaf(hv.y, w1.y, a1);
                a2 = fmaf(hv.y, w2.y, a2); a3 = fmaf(hv.y, w3.y, a3);
                a0 = fmaf(hv.z, w0.z, a0); a1 = fmaf(hv.z, w1.z, a1);
                a2 = fmaf(hv.z, w2.z, a2); a3 = fmaf(hv.z, w3.z, a3);
                a0 = fmaf(hv.w, w0.w, a0); a1 = fmaf(hv.w, w1.w, a1);
                a2 = fmaf(hv.w, w2.w, a2); a3 = fmaf(hv.w, w3.w, a3);
            }
        }
        {
            const float* xr = xg + ((size_t)t * BB + b) * G4H + k0 + kl;
            float gi = a0 + xr[0];
            float gf = a1 + xr[1024];
            float gg = a2 + xr[2048];
            float go = a3 + xr[3072];
            gi = 1.f / (1.f + expf(-gi));
            gf = 1.f / (1.f + expf(-gf));
            gg = tanhf(gg);
            go = 1.f / (1.f + expf(-go));
            c_reg = gf * c_reg + gi * gg;
            float hv = go * tanhf(c_reg);
            __stcg(&h_buf[b * HH + k0 + kl], hv);
        }
        grid_barrier();

        {
            float* sh = stage;   // [8][1028]
            for (int idx = tid; idx < 8 * 256; idx += 512) {
                int r = idx >> 8, c4 = idx & 255;
                float4 v = __ldcg((const float4*)&h_buf[(size_t)(b0 + r) * HH + c4 * 4]);
                *(float4*)&sh[r * 1028 + c4 * 4] = v;
            }
            __syncthreads();

            const float* hr = &sh[pb * 1028];
            const float* wr = &sWhr[ppp * 1028];
            float s = 0.f;
#pragma unroll 4
            for (int i = 0; i < 64; i++) {
                int e = i * 16 + q * 4;
                float4 hv = *(const float4*)&hr[e];
                float4 wv = *(const float4*)&wr[e];
                s = fmaf(hv.x, wv.x, s);
                s = fmaf(hv.y, wv.y, s);
                s = fmaf(hv.z, wv.z, s);
                s = fmaf(hv.w, wv.w, s);
            }
            s += __shfl_xor_sync(0xffffffffu, s, 1);
            s += __shfl_xor_sync(0xffffffffu, s, 2);
            if (q == 0)
                __stcg(&hp_out[((size_t)t * BB + (b0 + pb)) * PP + p0 + ppp], s);
        }
        grid_barrier();
    }
}

// ---------------------------------------------------------------------------
// Launch
// ---------------------------------------------------------------------------
extern "C" void kernel_launch(void* const* d_in, const int* in_sizes, int n_in,
                              void* d_out, int out_size)
{
    const float* x     = (const float*)d_in[0];
    const float* W_ih0 = (const float*)d_in[1];
    const float* W_hh0 = (const float*)d_in[2];
    const float* b_ih0 = (const float*)d_in[3];
    const float* b_hh0 = (const float*)d_in[4];
    const float* W_hr0 = (const float*)d_in[5];
    const float* W_ihs = (const float*)d_in[6];
    const float* W_hhs = (const float*)d_in[7];
    const float* b_ihs = (const float*)d_in[8];
    const float* b_hhs = (const float*)d_in[9];
    const float* W_hrs = (const float*)d_in[10];

    float *xg, *hpA, *hpB, *hb;
    __nv_bfloat16 *Abf, *Wbf;
    cudaGetSymbolAddress((void**)&xg,  g_xg);
    cudaGetSymbolAddress((void**)&hpA, g_hpA);
    cudaGetSymbolAddress((void**)&hpB, g_hpB);
    cudaGetSymbolAddress((void**)&hb,  g_h);
    cudaGetSymbolAddress((void**)&Abf, g_Abf);
    cudaGetSymbolAddress((void**)&Wbf, g_Wbf);

    cudaFuncSetAttribute(lstm_scan_kernel,
                         cudaFuncAttributeMaxDynamicSharedMemorySize, SCAN_SMEM);

    dim3 ggrid(32, 128);   // N/128, M/128

    // ---- layer 0 ----
    conv_W_kernel<<<(G4H * DIN) / 256, 256>>>(W_ih0, Wbf, DIN);
    conv_A_kernel<<<(MROWS * DIN) / 256, 256>>>(x, Abf, DIN, 1);
    gemm_mma_kernel<<<ggrid, 256>>>(Abf, Wbf, b_ih0, b_hh0, xg, 3 * DIN);
    lstm_scan_kernel<<<128, 512, SCAN_SMEM>>>(xg, W_hh0, W_hr0, hpA, hb);

    // ---- layers 1..3 ----
    float* cur = hpA;
    float* nxt = hpB;
    for (int l = 0; l < 3; l++) {
        conv_W_kernel<<<(G4H * PP) / 256, 256>>>(W_ihs + (size_t)l * G4H * PP, Wbf, PP);
        conv_A_kernel<<<(MROWS * PP) / 256, 256>>>(cur, Abf, PP, 0);
        gemm_mma_kernel<<<ggrid, 256>>>(Abf, Wbf,
                                        b_ihs + (size_t)l * G4H,
                                        b_hhs + (size_t)l * G4H,
                                        xg, 3 * PP);
        lstm_scan_kernel<<<128, 512, SCAN_SMEM>>>(xg,
                                                  W_hhs + (size_t)l * G4H * PP,
                                                  W_hrs + (size_t)l * PP * HH,
                                                  nxt, hb);
        float* tmp = cur; cur = nxt; nxt = tmp;
    }

    // output = last timestep of final layer
    cudaMemcpyAsync(d_out, cur + (size_t)(TT - 1) * BB * PP,
                    (size_t)BB * PP * sizeof(float),
                    cudaMemcpyDeviceToDevice);
    (void)in_sizes; (void)n_in; (void)out_size;
}

// round 11
// speedup vs baseline: 1.1199x; 1.0362x over previous
#include <cuda_runtime.h>
#include <cuda_bf16.h>
#include <cstdint>

// Problem constants
#define BB   64      // batch
#define TT   256     // seq len
#define DIN  512     // input dim (layer 0)
#define HH   1024    // hidden
#define PP   256     // proj
#define G4H  4096    // 4*H
#define MROWS (TT*BB)  // 16384 GEMM rows
#define NBLK 128

// ---------------------------------------------------------------------------
// Scratch (__device__ globals; allocation is forbidden)
// ---------------------------------------------------------------------------
__device__ float g_xg[(size_t)MROWS * G4H];                 // [T*B, 4H] (unit-major permuted cols)
__device__ float g_hpA[(size_t)MROWS * PP];
__device__ float g_hpB[(size_t)MROWS * PP];
__device__ __align__(16) __nv_bfloat16 g_Abf[(size_t)MROWS * (3 * DIN)];
__device__ __align__(16) __nv_bfloat16 g_Wbf[(size_t)G4H * (3 * DIN)];
// scan tensor-core operands
__device__ __align__(16) __nv_bfloat16 g_Wgbf[4 * (size_t)G4H * 768];   // per-layer [4096][768] (rows unit-major)
__device__ __align__(16) __nv_bfloat16 g_Wrbf[4 * (size_t)PP * 3072];   // per-layer [256][3072]
__device__ __align__(16) __nv_bfloat16 g_hpbf[BB * 768];                // A' for gate mma
__device__ __align__(16) __nv_bfloat16 g_hbf[BB * 3072];                // A' for proj mma
// distributed barrier
__device__ unsigned g_flags[NBLK * 32];
__device__ unsigned g_rel;

// ---------------------------------------------------------------------------
// Helpers
// ---------------------------------------------------------------------------
__device__ __forceinline__ uint32_t smem_u32(const void* p) {
    uint32_t a;
    asm("{ .reg .u64 t; cvta.to.shared.u64 t, %1; cvt.u32.u64 %0, t; }" : "=r"(a) : "l"(p));
    return a;
}
__device__ __forceinline__ void cp_async16(uint32_t dst, const void* src) {
    asm volatile("cp.async.cg.shared.global [%0], [%1], 16;" :: "r"(dst), "l"(src));
}
__device__ __forceinline__ void ldm_x4(uint32_t addr, uint32_t& r0, uint32_t& r1,
                                       uint32_t& r2, uint32_t& r3) {
    asm volatile("ldmatrix.sync.aligned.m8n8.x4.shared.b16 {%0,%1,%2,%3}, [%4];"
                 : "=r"(r0), "=r"(r1), "=r"(r2), "=r"(r3) : "r"(addr));
}
__device__ __forceinline__ void ldm_x2(uint32_t addr, uint32_t& r0, uint32_t& r1) {
    asm volatile("ldmatrix.sync.aligned.m8n8.x2.shared.b16 {%0,%1}, [%2];"
                 : "=r"(r0), "=r"(r1) : "r"(addr));
}
__device__ __forceinline__ void mma16816(float* d, const uint32_t* a,
                                         uint32_t b0, uint32_t b1) {
    asm volatile(
        "mma.sync.aligned.m16n8k16.row.col.f32.bf16.bf16.f32 "
        "{%0,%1,%2,%3}, {%4,%5,%6,%7}, {%8,%9}, {%0,%1,%2,%3};"
        : "+f"(d[0]), "+f"(d[1]), "+f"(d[2]), "+f"(d[3])
        : "r"(a[0]), "r"(a[1]), "r"(a[2]), "r"(a[3]), "r"(b0), "r"(b1));
}

// ---------------------------------------------------------------------------
// Distributed grid barrier: per-block flag (monotone counter), block 0 releases.
// ---------------------------------------------------------------------------
__device__ __forceinline__ void bar_arrive(int j, unsigned p) {
    __syncthreads();
    __threadfence();
    if (threadIdx.x == 0)
        ((volatile unsigned*)g_flags)[j * 32] = p;
}
__device__ __forceinline__ void bar_wait(int j, unsigned p) {
    if (j == 0) {
        if (threadIdx.x < NBLK) {
            volatile unsigned* f = ((volatile unsigned*)g_flags) + threadIdx.x * 32;
            while (*f < p) { }
        }
        __syncthreads();
        __threadfence();
        if (threadIdx.x == 0) *(volatile unsigned*)&g_rel = p;
        __syncthreads();
    } else {
        if (threadIdx.x == 0) {
            while (*(volatile unsigned*)&g_rel < p) { }
        }
        __syncthreads();
        __threadfence();
    }
}

__global__ void reset_barrier_kernel() {
    int i = threadIdx.x;
    if (i < NBLK) g_flags[i * 32] = 0;
    if (i == 0) g_rel = 0;
}

// ---------------------------------------------------------------------------
// fp32 -> split bf16 conversions for the input GEMM (same as passing R9).
// A': [hi|hi|lo], W': [hi|lo|hi]. W rows additionally permuted to unit-major.
// ---------------------------------------------------------------------------
__global__ void conv_A_kernel(const float* __restrict__ in, __nv_bfloat16* __restrict__ out,
                              int K, int remap) {
    int idx = blockIdx.x * 256 + threadIdx.x;
    if (idx >= MROWS * K) return;
    int m = idx / K;
    int k = idx - m * K;
    float a = in[idx];
    int r = remap ? (((m & 255) << 6) | (m >> 8)) : m;   // (b,t) -> row t*64+b
    __nv_bfloat16 hi = __float2bfloat16(a);
    __nv_bfloat16 lo = __float2bfloat16(a - __bfloat162float(hi));
    size_t base = (size_t)r * (3 * K);
    out[base + k] = hi;
    out[base + K + k] = hi;
    out[base + 2 * K + k] = lo;
}

__global__ void conv_W_kernel(const float* __restrict__ in, __nv_bfloat16* __restrict__ out,
                              int K) {
    int idx = blockIdx.x * 256 + threadIdx.x;
    if (idx >= G4H * K) return;
    int n = idx / K;
    int k = idx - n * K;
    float a = in[idx];
    __nv_bfloat16 hi = __float2bfloat16(a);
    __nv_bfloat16 lo = __float2bfloat16(a - __bfloat162float(hi));
    int np = 4 * (n & 1023) + (n >> 10);     // gate-major -> unit-major row permutation
    size_t base = (size_t)np * (3 * K);
    out[base + k] = hi;
    out[base + K + k] = lo;
    out[base + 2 * K + k] = hi;
}

// Scan weight conversions
__global__ void conv_Whh_kernel(const float* __restrict__ in, __nv_bfloat16* __restrict__ out) {
    int idx = blockIdx.x * 256 + threadIdx.x;    // over 4096*256
    if (idx >= G4H * PP) return;
    int n = idx >> 8, k = idx & 255;
    float a = in[idx];
    __nv_bfloat16 hi = __float2bfloat16(a);
    __nv_bfloat16 lo = __float2bfloat16(a - __bfloat162float(hi));
    int np = 4 * (n & 1023) + (n >> 10);
    size_t base = (size_t)np * 768;
    out[base + k] = hi;          // [Whi | Wlo | Whi]
    out[base + 256 + k] = lo;
    out[base + 512 + k] = hi;
}
__global__ void conv_Whr_kernel(const float* __restrict__ in, __nv_bfloat16* __restrict__ out) {
    int idx = blockIdx.x * 256 + threadIdx.x;    // over 256*1024
    if (idx >= PP * HH) return;
    int n = idx >> 10, k = idx & 1023;
    float a = in[idx];
    __nv_bfloat16 hi = __float2bfloat16(a);
    __nv_bfloat16 lo = __float2bfloat16(a - __bfloat162float(hi));
    size_t base = (size_t)n * 3072;
    out[base + k] = hi;
    out[base + 1024 + k] = lo;
    out[base + 2048 + k] = hi;
}

// ---------------------------------------------------------------------------
// Input-projection GEMM via mma.sync (passing R9 kernel; bias epilogue now
// applies inverse unit-major permutation since W rows are permuted).
// ---------------------------------------------------------------------------
#define LDS_ROW 40
#define TILE_BYTES (128 * LDS_ROW * 2)

__global__ __launch_bounds__(256) void gemm_mma_kernel(
    const __nv_bfloat16* __restrict__ A,
    const __nv_bfloat16* __restrict__ W,
    const float* __restrict__ b1, const float* __restrict__ b2,
    float* __restrict__ C, int K3)
{
    __shared__ alignas(16) __nv_bfloat16 sA[2][128][LDS_ROW];
    __shared__ alignas(16) __nv_bfloat16 sB[2][128][LDS_ROW];

    const int tid  = threadIdx.x;
    const int wid  = tid >> 5;
    const int lane = tid & 31;
    const int m0 = blockIdx.y * 128;
    const int n0 = blockIdx.x * 128;
    const int wm = (wid >> 2) * 64;
    const int wn = (wid & 3) * 32;

    const uint32_t sA_u = smem_u32(sA);
    const uint32_t sB_u = smem_u32(sB);

    float acc[4][4][4];
#pragma unroll
    for (int mi = 0; mi < 4; mi++)
#pragma unroll
        for (int nj = 0; nj < 4; nj++)
#pragma unroll
            for (int e = 0; e < 4; e++) acc[mi][nj][e] = 0.f;

    const int nchunks = K3 >> 5;

    const uint32_t a_off = (uint32_t)((wm + (lane & 15)) * LDS_ROW + ((lane >> 4) * 8)) * 2;
    const uint32_t b_off = (uint32_t)((wn + ((lane >> 3) & 1) * 8 + (lane & 7)) * LDS_ROW
                                      + ((lane >> 4) * 8)) * 2;

    {
        const __nv_bfloat16* Ag = A + (size_t)m0 * K3;
        const __nv_bfloat16* Wg = W + (size_t)n0 * K3;
#pragma unroll
        for (int i = 0; i < 2; i++) {
            int seg = i * 256 + tid;
            int row = seg >> 2, s = seg & 3;
            uint32_t off = (uint32_t)(row * LDS_ROW + s * 8) * 2;
            cp_async16(sA_u + off, Ag + (size_t)row * K3 + s * 8);
            cp_async16(sB_u + off, Wg + (size_t)row * K3 + s * 8);
        }
        asm volatile("cp.async.commit_group;" ::: "memory");
    }

    for (int c = 0; c < nchunks; c++) {
        const int buf = c & 1;
        if (c + 1 < nchunks) {
            const int nb = (c + 1) & 1;
            const __nv_bfloat16* Ag = A + (size_t)m0 * K3 + (c + 1) * 32;
            const __nv_bfloat16* Wg = W + (size_t)n0 * K3 + (c + 1) * 32;
#pragma unroll
            for (int i = 0; i < 2; i++) {
                int seg = i * 256 + tid;
                int row = seg >> 2, s = seg & 3;
                uint32_t off = (uint32_t)(nb * TILE_BYTES + (row * LDS_ROW + s * 8) * 2);
                cp_async16(sA_u + off, Ag + (size_t)row * K3 + s * 8);
                cp_async16(sB_u + off, Wg + (size_t)row * K3 + s * 8);
            }
            asm volatile("cp.async.commit_group;" ::: "memory");
            asm volatile("cp.async.wait_group 1;" ::: "memory");
        } else {
            asm volatile("cp.async.wait_group 0;" ::: "memory");
        }
        __syncthreads();

        const uint32_t abase = sA_u + buf * TILE_BYTES;
        const uint32_t bbase = sB_u + buf * TILE_BYTES;
#pragma unroll
        for (int ks = 0; ks < 2; ks++) {
            const uint32_t koff = (uint32_t)(ks * 16 * 2);
            uint32_t a[4][4];
#pragma unroll
            for (int mi = 0; mi < 4; mi++)
                ldm_x4(abase + a_off + koff + (uint32_t)(mi * 16 * LDS_ROW * 2),
                       a[mi][0], a[mi][1], a[mi][2], a[mi][3]);
            uint32_t bfrag[4][2];
#pragma unroll
            for (int g = 0; g < 2; g++) {
                uint32_t r0, r1, r2, r3;
                ldm_x4(bbase + b_off + koff + (uint32_t)(g * 16 * LDS_ROW * 2),
                       r0, r1, r2, r3);
                bfrag[g * 2 + 0][0] = r0; bfrag[g * 2 + 0][1] = r2;
                bfrag[g * 2 + 1][0] = r1; bfrag[g * 2 + 1][1] = r3;
            }
#pragma unroll
            for (int mi = 0; mi < 4; mi++)
#pragma unroll
                for (int nj = 0; nj < 4; nj++)
                    mma16816(acc[mi][nj], a[mi], bfrag[nj][0], bfrag[nj][1]);
        }
        __syncthreads();
    }

    // Epilogue: bias with inverse permutation (col n' -> orig (n'&3)*1024 + n'>>2)
    float bs0[4], bs1[4];
#pragma unroll
    for (int nj = 0; nj < 4; nj++) {
        int n = n0 + wn + nj * 8 + (lane & 3) * 2;
        int o0 = ((n & 3) << 10) | (n >> 2);
        int o1 = (((n + 1) & 3) << 10) | ((n + 1) >> 2);
        bs0[nj] = b1[o0] + b2[o0];
        bs1[nj] = b1[o1] + b2[o1];
    }
#pragma unroll
    for (int mi = 0; mi < 4; mi++) {
        int mrow = m0 + wm + mi * 16 + (lane >> 2);
#pragma unroll
        for (int nj = 0; nj < 4; nj++) {
            int n = n0 + wn + nj * 8 + (lane & 3) * 2;
            float2 v0 = make_float2(acc[mi][nj][0] + bs0[nj], acc[mi][nj][1] + bs1[nj]);
            float2 v1 = make_float2(acc[mi][nj][2] + bs0[nj], acc[mi][nj][3] + bs1[nj]);
            *(float2*)&C[(size_t)mrow * G4H + n]       = v0;
            *(float2*)&C[(size_t)(mrow + 8) * G4H + n] = v1;
        }
    }
}

// ---------------------------------------------------------------------------
// Tensor-core persistent LSTM scan.
// 128 blocks x 256 threads (8 warps = 4M x 2N for gate mma).
// Block j: gate cols [j*32, j*32+32) (unit-major: units j*8..j*8+8, 4 gates),
//          cell update local, writes h split-bf16.
// Blocks j<32: projection cols [j*8, j*8+8), K=3072 streamed.
// ---------------------------------------------------------------------------
#define OFF_WG 0
#define SZ_WG  (32 * 776 * 2)          // 49664
#define OFF_WR (OFF_WG + SZ_WG)
#define SZ_WR  (8 * 3080 * 2)          // 49280
#define OFF_ST (OFF_WR + SZ_WR)
#define SZ_ST  (2 * 64 * 264 * 2)      // 67584
#define OFF_SH (OFF_ST + SZ_ST)
#define SZ_SH  (64 * 9 * 4)            // 2304
#define OFF_SP (OFF_SH + SZ_SH)
#define SZ_SP  (64 * 9 * 4)
#define SCAN_SMEM (OFF_SP + SZ_SP)     // 171136

__global__ __launch_bounds__(256, 1) void lstm_scan_tc(
    const float* __restrict__ xg,
    const __nv_bfloat16* __restrict__ Wg,
    const __nv_bfloat16* __restrict__ Wr,
    float* __restrict__ hp_out,
    unsigned pbase)
{
    extern __shared__ char dsm[];
    float* sH = (float*)(dsm + OFF_SH);
    float* sP = (float*)(dsm + OFF_SP);
    const uint32_t sWg_u = smem_u32(dsm + OFF_WG);
    const uint32_t sWr_u = smem_u32(dsm + OFF_WR);
    const uint32_t st_u  = smem_u32(dsm + OFF_ST);

    const int tid = threadIdx.x;
    const int lane = tid & 31;
    const int w = tid >> 5;
    const int j = blockIdx.x;
    const bool isproj = (j < 32);
    const int wm = (w & 3) * 16;    // gate m-tile row base
    const int wn = (w >> 2) * 16;   // gate n-half base

    // ---- load persistent weight slices ----
    for (int i = tid; i < 3072; i += 256) {            // Wg: 32 rows x 96 segs
        int r = i / 96, s = i % 96;
        cp_async16(sWg_u + (uint32_t)(r * 776 + s * 8) * 2,
                   Wg + (size_t)(j * 32 + r) * 768 + s * 8);
    }
    if (isproj) {
        for (int i = tid; i < 3072; i += 256) {        // Wr: 8 rows x 384 segs
            int r = i / 384, s = i % 384;
            cp_async16(sWr_u + (uint32_t)(r * 3080 + s * 8) * 2,
                       Wr + (size_t)(j * 8 + r) * 3072 + s * 8);
        }
    }
    asm volatile("cp.async.commit_group;\ncp.async.wait_group 0;" ::: "memory");
    __syncthreads();

    float cst[4] = {0.f, 0.f, 0.f, 0.f};   // cell state (even lanes): [nj*2+rp]

    for (int t = 0; t < TT; t++) {
        float acc[2][4];
#pragma unroll
        for (int nj = 0; nj < 2; nj++)
#pragma unroll
            for (int e = 0; e < 4; e++) acc[nj][e] = 0.f;

        // ---- gate mma: hp' @ Wg' (skip at t=0: hp = 0) ----
        if (t > 0) {
            // preload chunk 0 of hp' [64][128]
            for (int i = tid; i < 1024; i += 256) {
                int r = i >> 4, s = i & 15;
                cp_async16(st_u + (uint32_t)(r * 136 + s * 8) * 2,
                           g_hpbf + (size_t)r * 768 + s * 8);
            }
            asm volatile("cp.async.commit_group;" ::: "memory");
            for (int kc = 0; kc < 6; kc++) {
                if (kc < 5) {
                    int nb = (kc + 1) & 1;
                    for (int i = tid; i < 1024; i += 256) {
                        int r = i >> 4, s = i & 15;
                        cp_async16(st_u + (uint32_t)(nb * 17408 + (r * 136 + s * 8) * 2),
                                   g_hpbf + (size_t)r * 768 + (kc + 1) * 128 + s * 8);
                    }
                    asm volatile("cp.async.commit_group;\ncp.async.wait_group 1;" ::: "memory");
                } else {
                    asm volatile("cp.async.wait_group 0;" ::: "memory");
                }
                __syncthreads();
                const uint32_t abase = st_u + (uint32_t)((kc & 1) * 17408);
#pragma unroll
                for (int ks = 0; ks < 8; ks++) {
                    uint32_t a[4], r0, r1, r2, r3;
                    ldm_x4(abase + (uint32_t)((wm + (lane & 15)) * 136
                                              + (lane >> 4) * 8 + ks * 16) * 2,
                           a[0], a[1], a[2], a[3]);
                    ldm_x4(sWg_u + (uint32_t)((wn + ((lane >> 3) & 1) * 8 + (lane & 7)) * 776
                                              + (lane >> 4) * 8 + kc * 128 + ks * 16) * 2,
                           r0, r1, r2, r3);
                    mma16816(acc[0], a, r0, r2);
                    mma16816(acc[1], a, r1, r3);
                }
                __syncthreads();
            }
        }

        // ---- add xg, cell update (lane pairs: even=(i,f), odd=(g,o)) ----
        {
            int rbase = wm + (lane >> 2);
#pragma unroll
            for (int nj = 0; nj < 2; nj++) {
#pragma unroll
                for (int rp = 0; rp < 2; rp++) {
                    int row = rbase + rp * 8;
                    int cl = wn + nj * 8 + (lane & 3) * 2;
                    const float* xr = xg + (size_t)(t * 64 + row) * G4H + j * 32 + cl;
                    float x0 = acc[nj][rp * 2 + 0] + __ldg(xr);
                    float x1 = acc[nj][rp * 2 + 1] + __ldg(xr + 1);
                    float y0 = __shfl_xor_sync(0xffffffffu, x0, 1);
                    float y1 = __shfl_xor_sync(0xffffffffu, x1, 1);
                    if (!(lane & 1)) {
                        float gi = 1.f / (1.f + __expf(-x0));
                        float gf = 1.f / (1.f + __expf(-x1));
                        float gg = tanhf(y0);
                        float go = 1.f / (1.f + __expf(-y1));
                        float c = gf * cst[nj * 2 + rp] + gi * gg;
                        cst[nj * 2 + rp] = c;
                        float h = go * tanhf(c);
                        int u = cl >> 2;
                        sH[row * 9 + u] = h;
                    }
                }
            }
        }
        __syncthreads();

        // ---- h split-bf16 writeback: rows 0..63, units j*8..+8 ----
        if (tid < 64) {
            __align__(16) __nv_bfloat16 hi8[8], lo8[8];
#pragma unroll
            for (int u = 0; u < 8; u++) {
                float hv = sH[tid * 9 + u];
                hi8[u] = __float2bfloat16(hv);
                lo8[u] = __float2bfloat16(hv - __bfloat162float(hi8[u]));
            }
            __nv_bfloat16* dst = g_hbf + (size_t)tid * 3072 + j * 8;
            __stcg((uint4*)dst,          *(const uint4*)hi8);
            __stcg((uint4*)(dst + 1024), *(const uint4*)hi8);
            __stcg((uint4*)(dst + 2048), *(const uint4*)lo8);
        }

        if (isproj) {
            bar_arrive(j, pbase + 2 * t + 1);
            bar_wait(j, pbase + 2 * t + 1);

            // ---- projection: hp = h' @ Wr'  (M=64, N=8, K=3072, 12 chunks) ----
            float accP[4] = {0.f, 0.f, 0.f, 0.f};
            for (int i = tid; i < 2048; i += 256) {
                int r = i >> 5, s = i & 31;
                cp_async16(st_u + (uint32_t)(r * 264 + s * 8) * 2,
                           g_hbf + (size_t)r * 3072 + s * 8);
            }
            asm volatile("cp.async.commit_group;" ::: "memory");
            for (int cc = 0; cc < 12; cc++) {
                if (cc < 11) {
                    int nb = (cc + 1) & 1;
                    for (int i = tid; i < 2048; i += 256) {
                        int r = i >> 5, s = i & 31;
                        cp_async16(st_u + (uint32_t)(nb * 33792 + (r * 264 + s * 8) * 2),
                                   g_hbf + (size_t)r * 3072 + (cc + 1) * 256 + s * 8);
                    }
                    asm volatile("cp.async.commit_group;\ncp.async.wait_group 1;" ::: "memory");
                } else {
                    asm volatile("cp.async.wait_group 0;" ::: "memory");
                }
                __syncthreads();
                if (w < 4) {
                    const uint32_t abase = st_u + (uint32_t)((cc & 1) * 33792);
#pragma unroll
                    for (int ks = 0; ks < 16; ks++) {
                        uint32_t a[4], b0, b1;
                        ldm_x4(abase + (uint32_t)((w * 16 + (lane & 15)) * 264
                                                  + (lane >> 4) * 8 + ks * 16) * 2,
                               a[0], a[1], a[2], a[3]);
                        ldm_x2(sWr_u + (uint32_t)((lane & 7) * 3080 + ((lane >> 3) & 1) * 8
                                                  + cc * 256 + ks * 16) * 2,
                               b0, b1);
                        mma16816(accP, a, b0, b1);
                    }
                }
                __syncthreads();
            }
            if (w < 4) {
                int row = w * 16 + (lane >> 2);
                int c0 = (lane & 3) * 2;
                sP[row * 9 + c0]           = accP[0];
                sP[row * 9 + c0 + 1]       = accP[1];
                sP[(row + 8) * 9 + c0]     = accP[2];
                sP[(row + 8) * 9 + c0 + 1] = accP[3];
            }
            __syncthreads();
            if (tid < 64) {
                float pv[8];
#pragma unroll
                for (int u = 0; u < 8; u++) pv[u] = sP[tid * 9 + u];
                // fp32 hp_out
                float* dp = hp_out + (size_t)(t * 64 + tid) * PP + j * 8;
                __stcg((float4*)dp,       make_float4(pv[0], pv[1], pv[2], pv[3]));
                __stcg((float4*)(dp + 4), make_float4(pv[4], pv[5], pv[6], pv[7]));
                // split-bf16 hp'
                __align__(16) __nv_bfloat16 hi8[8], lo8[8];
#pragma unroll
                for (int u = 0; u < 8; u++) {
                    hi8[u] = __float2bfloat16(pv[u]);
                    lo8[u] = __float2bfloat16(pv[u] - __bfloat162float(hi8[u]));
                }
                __nv_bfloat16* db = g_hpbf + (size_t)tid * 768 + j * 8;
                __stcg((uint4*)db,         *(const uint4*)hi8);
                __stcg((uint4*)(db + 256), *(const uint4*)hi8);
                __stcg((uint4*)(db + 512), *(const uint4*)lo8);
            }
            bar_arrive(j, pbase + 2 * t + 2);
            bar_wait(j, pbase + 2 * t + 2);
        } else {
            // non-proj: single arrive at the higher phase (monotone flags)
            bar_arrive(j, pbase + 2 * t + 2);
            bar_wait(j, pbase + 2 * t + 2);
        }
    }
}

// ---------------------------------------------------------------------------
// Launch
// ---------------------------------------------------------------------------
extern "C" void kernel_launch(void* const* d_in, const int* in_sizes, int n_in,
                              void* d_out, int out_size)
{
    const float* x     = (const float*)d_in[0];
    const float* W_ih0 = (const float*)d_in[1];
    const float* W_hh0 = (const float*)d_in[2];
    const float* b_ih0 = (const float*)d_in[3];
    const float* b_hh0 = (const float*)d_in[4];
    const float* W_hr0 = (const float*)d_in[5];
    const float* W_ihs = (const float*)d_in[6];
    const float* W_hhs = (const float*)d_in[7];
    const float* b_ihs = (const float*)d_in[8];
    const float* b_hhs = (const float*)d_in[9];
    const float* W_hrs = (const float*)d_in[10];

    float *xg, *hpA, *hpB;
    __nv_bfloat16 *Abf, *Wbf, *Wgbf, *Wrbf;
    cudaGetSymbolAddress((void**)&xg,   g_xg);
    cudaGetSymbolAddress((void**)&hpA,  g_hpA);
    cudaGetSymbolAddress((void**)&hpB,  g_hpB);
    cudaGetSymbolAddress((void**)&Abf,  g_Abf);
    cudaGetSymbolAddress((void**)&Wbf,  g_Wbf);
    cudaGetSymbolAddress((void**)&Wgbf, g_Wgbf);
    cudaGetSymbolAddress((void**)&Wrbf, g_Wrbf);

    cudaFuncSetAttribute(lstm_scan_tc,
                         cudaFuncAttributeMaxDynamicSharedMemorySize, SCAN_SMEM);

    dim3 ggrid(32, 128);   // N/128, M/128

    // barrier reset (fresh every graph replay)
    reset_barrier_kernel<<<1, 256>>>();

    // scan weight conversions (all layers)
    conv_Whh_kernel<<<(G4H * PP) / 256, 256>>>(W_hh0, Wgbf);
    conv_Whr_kernel<<<(PP * HH) / 256, 256>>>(W_hr0, Wrbf);
    for (int l = 0; l < 3; l++) {
        conv_Whh_kernel<<<(G4H * PP) / 256, 256>>>(
            W_hhs + (size_t)l * G4H * PP, Wgbf + (size_t)(l + 1) * G4H * 768);
        conv_Whr_kernel<<<(PP * HH) / 256, 256>>>(
            W_hrs + (size_t)l * PP * HH, Wrbf + (size_t)(l + 1) * PP * 3072);
    }

    // ---- layer 0 ----
    conv_W_kernel<<<(G4H * DIN) / 256, 256>>>(W_ih0, Wbf, DIN);
    conv_A_kernel<<<(MROWS * DIN) / 256, 256>>>(x, Abf, DIN, 1);
    gemm_mma_kernel<<<ggrid, 256>>>(Abf, Wbf, b_ih0, b_hh0, xg, 3 * DIN);
    lstm_scan_tc<<<NBLK, 256, SCAN_SMEM>>>(xg, Wgbf, Wrbf, hpA, 0u);

    // ---- layers 1..3 ----
    float* cur = hpA;
    float* nxt = hpB;
    for (int l = 0; l < 3; l++) {
        conv_W_kernel<<<(G4H * PP) / 256, 256>>>(W_ihs + (size_t)l * G4H * PP, Wbf, PP);
        conv_A_kernel<<<(MROWS * PP) / 256, 256>>>(cur, Abf, PP, 0);
        gemm_mma_kernel<<<ggrid, 256>>>(Abf, Wbf,
                                        b_ihs + (size_t)l * G4H,
                                        b_hhs + (size_t)l * G4H,
                                        xg, 3 * PP);
        lstm_scan_tc<<<NBLK, 256, SCAN_SMEM>>>(xg,
                                               Wgbf + (size_t)(l + 1) * G4H * 768,
                                               Wrbf + (size_t)(l + 1) * PP * 3072,
                                               nxt, (unsigned)((l + 1) * 512));
        float* tmp = cur; cur = nxt; nxt = tmp;
    }

    // output = last timestep of final layer
    cudaMemcpyAsync(d_out, cur + (size_t)(TT - 1) * BB * PP,
                    (size_t)BB * PP * sizeof(float),
                    cudaMemcpyDeviceToDevice);
    (void)in_sizes; (void)n_in; (void)out_size;
}

// round 13
// speedup vs baseline: 1.3328x; 1.1901x over previous
#include <cuda_runtime.h>
#include <cuda_bf16.h>
#include <cstdint>

// Problem constants
#define BB   64      // batch
#define TT   256     // seq len
#define DIN  512     // input dim (layer 0)
#define HH   1024    // hidden
#define PP   256     // proj
#define G4H  4096    // 4*H
#define MROWS (TT*BB)  // 16384 GEMM rows
#define NBLK 128

// ---------------------------------------------------------------------------
// Scratch (__device__ globals; allocation is forbidden)
// ---------------------------------------------------------------------------
__device__ float g_xg[(size_t)MROWS * G4H];                 // [T*B, 4H] (unit-major permuted cols)
__device__ float g_hpA[(size_t)MROWS * PP];
__device__ float g_hpB[(size_t)MROWS * PP];
__device__ __align__(16) __nv_bfloat16 g_Abf[(size_t)MROWS * (3 * DIN)];
__device__ __align__(16) __nv_bfloat16 g_Wbf[(size_t)G4H * (3 * DIN)];
// scan tensor-core operands
__device__ __align__(16) __nv_bfloat16 g_Wgbf[4 * (size_t)G4H * 768];   // per-layer [4096][768] (rows unit-major)
__device__ __align__(16) __nv_bfloat16 g_Wrbf[4 * (size_t)PP * 3072];   // per-layer [256][3072]
__device__ __align__(16) __nv_bfloat16 g_hpbf[BB * 768];                // A' for gate mma
__device__ __align__(16) __nv_bfloat16 g_hbf[BB * 3072];                // A' for proj mma
// distributed barrier
__device__ unsigned g_flags[NBLK * 32];
__device__ unsigned g_rel;

// ---------------------------------------------------------------------------
// Helpers
// ---------------------------------------------------------------------------
__device__ __forceinline__ uint32_t smem_u32(const void* p) {
    uint32_t a;
    asm("{ .reg .u64 t; cvta.to.shared.u64 t, %1; cvt.u32.u64 %0, t; }" : "=r"(a) : "l"(p));
    return a;
}
__device__ __forceinline__ void cp_async16(uint32_t dst, const void* src) {
    asm volatile("cp.async.cg.shared.global [%0], [%1], 16;" :: "r"(dst), "l"(src));
}
__device__ __forceinline__ void cp_commit() {
    asm volatile("cp.async.commit_group;" ::: "memory");
}
template <int N>
__device__ __forceinline__ void cp_wait() {
    asm volatile("cp.async.wait_group %0;" :: "n"(N) : "memory");
}
__device__ __forceinline__ void ldm_x4(uint32_t addr, uint32_t& r0, uint32_t& r1,
                                       uint32_t& r2, uint32_t& r3) {
    asm volatile("ldmatrix.sync.aligned.m8n8.x4.shared.b16 {%0,%1,%2,%3}, [%4];"
                 : "=r"(r0), "=r"(r1), "=r"(r2), "=r"(r3) : "r"(addr));
}
__device__ __forceinline__ void ldm_x2(uint32_t addr, uint32_t& r0, uint32_t& r1) {
    asm volatile("ldmatrix.sync.aligned.m8n8.x2.shared.b16 {%0,%1}, [%2];"
                 : "=r"(r0), "=r"(r1) : "r"(addr));
}
__device__ __forceinline__ void mma16816(float* d, const uint32_t* a,
                                         uint32_t b0, uint32_t b1) {
    asm volatile(
        "mma.sync.aligned.m16n8k16.row.col.f32.bf16.bf16.f32 "
        "{%0,%1,%2,%3}, {%4,%5,%6,%7}, {%8,%9}, {%0,%1,%2,%3};"
        : "+f"(d[0]), "+f"(d[1]), "+f"(d[2]), "+f"(d[3])
        : "r"(a[0]), "r"(a[1]), "r"(a[2]), "r"(a[3]), "r"(b0), "r"(b1));
}

// ---------------------------------------------------------------------------
// Distributed grid barrier: per-block flag (monotone counter), block 0 releases.
// ---------------------------------------------------------------------------
__device__ __forceinline__ void bar_arrive(int j, unsigned p) {
    __syncthreads();
    __threadfence();
    if (threadIdx.x == 0)
        ((volatile unsigned*)g_flags)[j * 32] = p;
}
__device__ __forceinline__ void bar_wait(int j, unsigned p) {
    if (j == 0) {
        if (threadIdx.x < NBLK) {
            volatile unsigned* f = ((volatile unsigned*)g_flags) + threadIdx.x * 32;
            while (*f < p) { }
        }
        __syncthreads();
        __threadfence();
        if (threadIdx.x == 0) *(volatile unsigned*)&g_rel = p;
        __syncthreads();
    } else {
        if (threadIdx.x == 0) {
            while (*(volatile unsigned*)&g_rel < p) { }
        }
        __syncthreads();
        __threadfence();
    }
}

__global__ void reset_barrier_kernel() {
    int i = threadIdx.x;
    if (i < NBLK) g_flags[i * 32] = 0;
    if (i == 0) g_rel = 0;
}

// ---------------------------------------------------------------------------
// fp32 -> split bf16 conversions for the input GEMM.
// A': [hi|hi|lo], W': [hi|lo|hi]. W rows permuted to unit-major.
// ---------------------------------------------------------------------------
__global__ void conv_A_kernel(const float* __restrict__ in, __nv_bfloat16* __restrict__ out,
                              int K, int remap) {
    int idx = blockIdx.x * 256 + threadIdx.x;
    if (idx >= MROWS * K) return;
    int m = idx / K;
    int k = idx - m * K;
    float a = in[idx];
    int r = remap ? (((m & 255) << 6) | (m >> 8)) : m;   // (b,t) -> row t*64+b
    __nv_bfloat16 hi = __float2bfloat16(a);
    __nv_bfloat16 lo = __float2bfloat16(a - __bfloat162float(hi));
    size_t base = (size_t)r * (3 * K);
    out[base + k] = hi;
    out[base + K + k] = hi;
    out[base + 2 * K + k] = lo;
}

__global__ void conv_W_kernel(const float* __restrict__ in, __nv_bfloat16* __restrict__ out,
                              int K) {
    int idx = blockIdx.x * 256 + threadIdx.x;
    if (idx >= G4H * K) return;
    int n = idx / K;
    int k = idx - n * K;
    float a = in[idx];
    __nv_bfloat16 hi = __float2bfloat16(a);
    __nv_bfloat16 lo = __float2bfloat16(a - __bfloat162float(hi));
    int np = 4 * (n & 1023) + (n >> 10);     // gate-major -> unit-major row permutation
    size_t base = (size_t)np * (3 * K);
    out[base + k] = hi;
    out[base + K + k] = lo;
    out[base + 2 * K + k] = hi;
}

// Scan weight conversions
__global__ void conv_Whh_kernel(const float* __restrict__ in, __nv_bfloat16* __restrict__ out) {
    int idx = blockIdx.x * 256 + threadIdx.x;    // over 4096*256
    if (idx >= G4H * PP) return;
    int n = idx >> 8, k = idx & 255;
    float a = in[idx];
    __nv_bfloat16 hi = __float2bfloat16(a);
    __nv_bfloat16 lo = __float2bfloat16(a - __bfloat162float(hi));
    int np = 4 * (n & 1023) + (n >> 10);
    size_t base = (size_t)np * 768;
    out[base + k] = hi;          // [Whi | Wlo | Whi]
    out[base + 256 + k] = lo;
    out[base + 512 + k] = hi;
}
__global__ void conv_Whr_kernel(const float* __restrict__ in, __nv_bfloat16* __restrict__ out) {
    int idx = blockIdx.x * 256 + threadIdx.x;    // over 256*1024
    if (idx >= PP * HH) return;
    int n = idx >> 10, k = idx & 1023;
    float a = in[idx];
    __nv_bfloat16 hi = __float2bfloat16(a);
    __nv_bfloat16 lo = __float2bfloat16(a - __bfloat162float(hi));
    size_t base = (size_t)n * 3072;
    out[base + k] = hi;
    out[base + 1024 + k] = lo;
    out[base + 2048 + k] = hi;
}

// ---------------------------------------------------------------------------
// Input-projection GEMM via mma.sync (unchanged, passing since R9/R11).
// ---------------------------------------------------------------------------
#define LDS_ROW 40
#define TILE_BYTES (128 * LDS_ROW * 2)

__global__ __launch_bounds__(256) void gemm_mma_kernel(
    const __nv_bfloat16* __restrict__ A,
    const __nv_bfloat16* __restrict__ W,
    const float* __restrict__ b1, const float* __restrict__ b2,
    float* __restrict__ C, int K3)
{
    __shared__ alignas(16) __nv_bfloat16 sA[2][128][LDS_ROW];
    __shared__ alignas(16) __nv_bfloat16 sB[2][128][LDS_ROW];

    const int tid  = threadIdx.x;
    const int wid  = tid >> 5;
    const int lane = tid & 31;
    const int m0 = blockIdx.y * 128;
    const int n0 = blockIdx.x * 128;
    const int wm = (wid >> 2) * 64;
    const int wn = (wid & 3) * 32;

    const uint32_t sA_u = smem_u32(sA);
    const uint32_t sB_u = smem_u32(sB);

    float acc[4][4][4];
#pragma unroll
    for (int mi = 0; mi < 4; mi++)
#pragma unroll
        for (int nj = 0; nj < 4; nj++)
#pragma unroll
            for (int e = 0; e < 4; e++) acc[mi][nj][e] = 0.f;

    const int nchunks = K3 >> 5;

    const uint32_t a_off = (uint32_t)((wm + (lane & 15)) * LDS_ROW + ((lane >> 4) * 8)) * 2;
    const uint32_t b_off = (uint32_t)((wn + ((lane >> 3) & 1) * 8 + (lane & 7)) * LDS_ROW
                                      + ((lane >> 4) * 8)) * 2;

    {
        const __nv_bfloat16* Ag = A + (size_t)m0 * K3;
        const __nv_bfloat16* Wg = W + (size_t)n0 * K3;
#pragma unroll
        for (int i = 0; i < 2; i++) {
            int seg = i * 256 + tid;
            int row = seg >> 2, s = seg & 3;
            uint32_t off = (uint32_t)(row * LDS_ROW + s * 8) * 2;
            cp_async16(sA_u + off, Ag + (size_t)row * K3 + s * 8);
            cp_async16(sB_u + off, Wg + (size_t)row * K3 + s * 8);
        }
        cp_commit();
    }

    for (int c = 0; c < nchunks; c++) {
        const int buf = c & 1;
        if (c + 1 < nchunks) {
            const int nb = (c + 1) & 1;
            const __nv_bfloat16* Ag = A + (size_t)m0 * K3 + (c + 1) * 32;
            const __nv_bfloat16* Wg = W + (size_t)n0 * K3 + (c + 1) * 32;
#pragma unroll
            for (int i = 0; i < 2; i++) {
                int seg = i * 256 + tid;
                int row = seg >> 2, s = seg & 3;
                uint32_t off = (uint32_t)(nb * TILE_BYTES + (row * LDS_ROW + s * 8) * 2);
                cp_async16(sA_u + off, Ag + (size_t)row * K3 + s * 8);
                cp_async16(sB_u + off, Wg + (size_t)row * K3 + s * 8);
            }
            cp_commit();
            cp_wait<1>();
        } else {
            cp_wait<0>();
        }
        __syncthreads();

        const uint32_t abase = sA_u + buf * TILE_BYTES;
        const uint32_t bbase = sB_u + buf * TILE_BYTES;
#pragma unroll
        for (int ks = 0; ks < 2; ks++) {
            const uint32_t koff = (uint32_t)(ks * 16 * 2);
            uint32_t a[4][4];
#pragma unroll
            for (int mi = 0; mi < 4; mi++)
                ldm_x4(abase + a_off + koff + (uint32_t)(mi * 16 * LDS_ROW * 2),
                       a[mi][0], a[mi][1], a[mi][2], a[mi][3]);
            uint32_t bfrag[4][2];
#pragma unroll
            for (int g = 0; g < 2; g++) {
                uint32_t r0, r1, r2, r3;
                ldm_x4(bbase + b_off + koff + (uint32_t)(g * 16 * LDS_ROW * 2),
                       r0, r1, r2, r3);
                bfrag[g * 2 + 0][0] = r0; bfrag[g * 2 + 0][1] = r2;
                bfrag[g * 2 + 1][0] = r1; bfrag[g * 2 + 1][1] = r3;
            }
#pragma unroll
            for (int mi = 0; mi < 4; mi++)
#pragma unroll
                for (int nj = 0; nj < 4; nj++)
                    mma16816(acc[mi][nj], a[mi], bfrag[nj][0], bfrag[nj][1]);
        }
        __syncthreads();
    }

    // Epilogue: bias with inverse permutation (col n' -> orig (n'&3)*1024 + n'>>2)
    float bs0[4], bs1[4];
#pragma unroll
    for (int nj = 0; nj < 4; nj++) {
        int n = n0 + wn + nj * 8 + (lane & 3) * 2;
        int o0 = ((n & 3) << 10) | (n >> 2);
        int o1 = (((n + 1) & 3) << 10) | ((n + 1) >> 2);
        bs0[nj] = b1[o0] + b2[o0];
        bs1[nj] = b1[o1] + b2[o1];
    }
#pragma unroll
    for (int mi = 0; mi < 4; mi++) {
        int mrow = m0 + wm + mi * 16 + (lane >> 2);
#pragma unroll
        for (int nj = 0; nj < 4; nj++) {
            int n = n0 + wn + nj * 8 + (lane & 3) * 2;
            float2 v0 = make_float2(acc[mi][nj][0] + bs0[nj], acc[mi][nj][1] + bs1[nj]);
            float2 v1 = make_float2(acc[mi][nj][2] + bs0[nj], acc[mi][nj][3] + bs1[nj]);
            *(float2*)&C[(size_t)mrow * G4H + n]       = v0;
            *(float2*)&C[(size_t)(mrow + 8) * G4H + n] = v1;
        }
    }
}

// ---------------------------------------------------------------------------
// Tensor-core persistent LSTM scan, deep-pipelined.
// 128 blocks x 256 threads. Uniform 128-col [64][136] bf16 chunks, 4 slots,
// lookahead-3, ONE __syncthreads per chunk.
// Block j: gate cols [j*32,+32) (units j*8..+8, 4 gates). Blocks j<32 also
// compute projection cols [j*8,+8) (K=3072, 24 chunks).
// ---------------------------------------------------------------------------
#define CH_ROW   136
#define CH_BYTES (64 * CH_ROW * 2)     // 17408

#define OFF_WG 0
#define SZ_WG  (32 * 776 * 2)          // 49664
#define OFF_WR (OFF_WG + SZ_WG)
#define SZ_WR  (8 * 3080 * 2)          // 49280
#define OFF_ST (OFF_WR + SZ_WR)
#define SZ_ST  (4 * CH_BYTES)          // 69632
#define OFF_SH (OFF_ST + SZ_ST)
#define SZ_SH  (64 * 9 * 4)            // 2304
#define OFF_SP (OFF_SH + SZ_SH)
#define SZ_SP  (64 * 9 * 4)
#define OFF_XG (OFF_SP + SZ_SP)
#define SZ_XG  (64 * 36 * 4)           // 9216
#define SCAN_SMEM (OFF_XG + SZ_XG)     // 182400

__global__ __launch_bounds__(256, 1) void lstm_scan_tc(
    const float* __restrict__ xg,
    const __nv_bfloat16* __restrict__ Wg,
    const __nv_bfloat16* __restrict__ Wr,
    float* __restrict__ hp_out,
    unsigned pbase)
{
    extern __shared__ char dsm[];
    float* sH = (float*)(dsm + OFF_SH);
    float* sP = (float*)(dsm + OFF_SP);
    float* sXg = (float*)(dsm + OFF_XG);
    const uint32_t sWg_u = smem_u32(dsm + OFF_WG);
    const uint32_t sWr_u = smem_u32(dsm + OFF_WR);
    const uint32_t st_u  = smem_u32(dsm + OFF_ST);
    const uint32_t sXg_u = smem_u32(dsm + OFF_XG);

    const int tid = threadIdx.x;
    const int lane = tid & 31;
    const int w = tid >> 5;
    const int j = blockIdx.x;
    const bool isproj = (j < 32);
    const int wm = (w & 3) * 16;
    const int wn = (w >> 2) * 16;

    // ---- load persistent weight slices ----
    for (int i = tid; i < 3072; i += 256) {            // Wg: 32 rows x 96 segs
        int r = i / 96, s = i % 96;
        cp_async16(sWg_u + (uint32_t)(r * 776 + s * 8) * 2,
                   Wg + (size_t)(j * 32 + r) * 768 + s * 8);
    }
    if (isproj) {
        for (int i = tid; i < 3072; i += 256) {        // Wr: 8 rows x 384 segs
            int r = i / 384, s = i % 384;
            cp_async16(sWr_u + (uint32_t)(r * 3080 + s * 8) * 2,
                       Wr + (size_t)(j * 8 + r) * 3072 + s * 8);
        }
    }
    cp_commit();
    cp_wait<0>();
    __syncthreads();

    float cst[4] = {0.f, 0.f, 0.f, 0.f};   // cell state (even lanes): [nj*2+rp]

    for (int t = 0; t < TT; t++) {
        float acc[2][4];
#pragma unroll
        for (int nj = 0; nj < 2; nj++)
#pragma unroll
            for (int e = 0; e < 4; e++) acc[nj][e] = 0.f;

        // chunk-load lambdas (manual): gate chunk kc -> slot kc&3
        // xg tile prefetch: 64 rows x 8 segs (16B) = 512 segs, 2/thread
        if (t > 0) {
            // preload gate chunks 0..2; chunk 0's group includes the xg tile
            {
                for (int k = 0; k < 2; k++) {
                    int i = k * 256 + tid;
                    int r = i >> 3, s = i & 7;
                    cp_async16(sXg_u + (uint32_t)(r * 144 + s * 16),
                               xg + (size_t)(t * 64 + r) * G4H + j * 32 + s * 4);
                }
                for (int k = 0; k < 4; k++) {
                    int i = k * 256 + tid;
                    int r = i >> 4, s = i & 15;
                    cp_async16(st_u + (uint32_t)(r * CH_ROW + s * 8) * 2,
                               g_hpbf + (size_t)r * 768 + s * 8);
                }
                cp_commit();
#pragma unroll
                for (int pc = 1; pc < 3; pc++) {
                    for (int k = 0; k < 4; k++) {
                        int i = k * 256 + tid;
                        int r = i >> 4, s = i & 15;
                        cp_async16(st_u + (uint32_t)(pc * CH_BYTES + (r * CH_ROW + s * 8) * 2),
                                   g_hpbf + (size_t)r * 768 + pc * 128 + s * 8);
                    }
                    cp_commit();
                }
            }
#pragma unroll
            for (int kc = 0; kc < 6; kc++) {
                if (kc <= 3) cp_wait<2>();
                else if (kc == 4) cp_wait<1>();
                else cp_wait<0>();
                __syncthreads();
                const uint32_t abase = st_u + (uint32_t)((kc & 3) * CH_BYTES);
#pragma unroll
                for (int ks = 0; ks < 8; ks++) {
                    uint32_t a[4], r0, r1, r2, r3;
                    ldm_x4(abase + (uint32_t)((wm + (lane & 15)) * CH_ROW
                                              + (lane >> 4) * 8 + ks * 16) * 2,
                           a[0], a[1], a[2], a[3]);
                    ldm_x4(sWg_u + (uint32_t)((wn + ((lane >> 3) & 1) * 8 + (lane & 7)) * 776
                                              + (lane >> 4) * 8 + kc * 128 + ks * 16) * 2,
                           r0, r1, r2, r3);
                    mma16816(acc[0], a, r0, r2);
                    mma16816(acc[1], a, r1, r3);
                }
                if (kc + 3 < 6) {
                    int nc = kc + 3;
                    uint32_t base = st_u + (uint32_t)((nc & 3) * CH_BYTES);
                    for (int k = 0; k < 4; k++) {
                        int i = k * 256 + tid;
                        int r = i >> 4, s = i & 15;
                        cp_async16(base + (uint32_t)(r * CH_ROW + s * 8) * 2,
                                   g_hpbf + (size_t)r * 768 + nc * 128 + s * 8);
                    }
                    cp_commit();
                }
            }
        } else {
            // t == 0: only the xg tile
            for (int k = 0; k < 2; k++) {
                int i = k * 256 + tid;
                int r = i >> 3, s = i & 7;
                cp_async16(sXg_u + (uint32_t)(r * 144 + s * 16),
                           xg + (size_t)(t * 64 + r) * G4H + j * 32 + s * 4);
            }
            cp_commit();
            cp_wait<0>();
            __syncthreads();
        }

        // ---- add xg (from SMEM), cell update (even=(i,f), odd=(g,o)) ----
        {
            int rbase = wm + (lane >> 2);
#pragma unroll
            for (int nj = 0; nj < 2; nj++) {
#pragma unroll
                for (int rp = 0; rp < 2; rp++) {
                    int row = rbase + rp * 8;
                    int cl = wn + nj * 8 + (lane & 3) * 2;
                    float2 xv = *(const float2*)&sXg[row * 36 + cl];
                    float x0 = acc[nj][rp * 2 + 0] + xv.x;
                    float x1 = acc[nj][rp * 2 + 1] + xv.y;
                    float y0 = __shfl_xor_sync(0xffffffffu, x0, 1);
                    float y1 = __shfl_xor_sync(0xffffffffu, x1, 1);
                    if (!(lane & 1)) {
                        float gi = 1.f / (1.f + __expf(-x0));
                        float gf = 1.f / (1.f + __expf(-x1));
                        float gg = tanhf(y0);
                        float go = 1.f / (1.f + __expf(-y1));
                        float c = gf * cst[nj * 2 + rp] + gi * gg;
                        cst[nj * 2 + rp] = c;
                        float h = go * tanhf(c);
                        int u = cl >> 2;
                        sH[row * 9 + u] = h;
                    }
                }
            }
        }
        __syncthreads();

        // ---- h split-bf16 writeback: rows 0..63, units j*8..+8 ----
        if (tid < 64) {
            __align__(16) __nv_bfloat16 hi8[8], lo8[8];
#pragma unroll
            for (int u = 0; u < 8; u++) {
                float hv = sH[tid * 9 + u];
                hi8[u] = __float2bfloat16(hv);
                lo8[u] = __float2bfloat16(hv - __bfloat162float(hi8[u]));
            }
            __nv_bfloat16* dst = g_hbf + (size_t)tid * 3072 + j * 8;
            __stcg((uint4*)dst,          *(const uint4*)hi8);
            __stcg((uint4*)(dst + 1024), *(const uint4*)hi8);
            __stcg((uint4*)(dst + 2048), *(const uint4*)lo8);
        }

        if (isproj) {
            bar_arrive(j, pbase + 2 * t + 1);
            bar_wait(j, pbase + 2 * t + 1);

            // ---- projection: hp = h' @ Wr'  (M=64, N=8, K=3072, 24 chunks) ----
            float accP[4] = {0.f, 0.f, 0.f, 0.f};
#pragma unroll
            for (int pc = 0; pc < 3; pc++) {
                for (int k = 0; k < 4; k++) {
                    int i = k * 256 + tid;
                    int r = i >> 4, s = i & 15;
                    cp_async16(st_u + (uint32_t)(pc * CH_BYTES + (r * CH_ROW + s * 8) * 2),
                               g_hbf + (size_t)r * 3072 + pc * 128 + s * 8);
                }
                cp_commit();
            }
            for (int cc = 0; cc < 24; cc++) {
                if (cc <= 21) cp_wait<2>();
                else if (cc == 22) cp_wait<1>();
                else cp_wait<0>();
                __syncthreads();
                if (w < 4) {
                    const uint32_t abase = st_u + (uint32_t)((cc & 3) * CH_BYTES);
#pragma unroll
                    for (int ks = 0; ks < 8; ks++) {
                        uint32_t a[4], b0, b1;
                        ldm_x4(abase + (uint32_t)((w * 16 + (lane & 15)) * CH_ROW
                                                  + (lane >> 4) * 8 + ks * 16) * 2,
                               a[0], a[1], a[2], a[3]);
                        ldm_x2(sWr_u + (uint32_t)((lane & 7) * 3080 + ((lane >> 3) & 1) * 8
                                                  + cc * 128 + ks * 16) * 2,
                               b0, b1);
                        mma16816(accP, a, b0, b1);
                    }
                }
                if (cc + 3 < 24) {
                    int nc = cc + 3;
                    uint32_t base = st_u + (uint32_t)((nc & 3) * CH_BYTES);
                    for (int k = 0; k < 4; k++) {
                        int i = k * 256 + tid;
                        int r = i >> 4, s = i & 15;
                        cp_async16(base + (uint32_t)(r * CH_ROW + s * 8) * 2,
                                   g_hbf + (size_t)r * 3072 + nc * 128 + s * 8);
                    }
                    cp_commit();
                }
            }
            if (w < 4) {
                int row = w * 16 + (lane >> 2);
                int c0 = (lane & 3) * 2;
                sP[row * 9 + c0]           = accP[0];
                sP[row * 9 + c0 + 1]       = accP[1];
                sP[(row + 8) * 9 + c0]     = accP[2];
                sP[(row + 8) * 9 + c0 + 1] = accP[3];
            }
            __syncthreads();
            if (tid < 64) {
                float pv[8];
#pragma unroll
                for (int u = 0; u < 8; u++) pv[u] = sP[tid * 9 + u];
                float* dp = hp_out + (size_t)(t * 64 + tid) * PP + j * 8;
                __stcg((float4*)dp,       make_float4(pv[0], pv[1], pv[2], pv[3]));
                __stcg((float4*)(dp + 4), make_float4(pv[4], pv[5], pv[6], pv[7]));
                __align__(16) __nv_bfloat16 hi8[8], lo8[8];
#pragma unroll
                for (int u = 0; u < 8; u++) {
                    hi8[u] = __float2bfloat16(pv[u]);
                    lo8[u] = __float2bfloat16(pv[u] - __bfloat162float(hi8[u]));
                }
                __nv_bfloat16* db = g_hpbf + (size_t)tid * 768 + j * 8;
                __stcg((uint4*)db,         *(const uint4*)hi8);
                __stcg((uint4*)(db + 256), *(const uint4*)hi8);
                __stcg((uint4*)(db + 512), *(const uint4*)lo8);
            }
            bar_arrive(j, pbase + 2 * t + 2);
            bar_wait(j, pbase + 2 * t + 2);
        } else {
            bar_arrive(j, pbase + 2 * t + 2);
            bar_wait(j, pbase + 2 * t + 2);
        }
    }
}

// ---------------------------------------------------------------------------
// Launch
// ---------------------------------------------------------------------------
extern "C" void kernel_launch(void* const* d_in, const int* in_sizes, int n_in,
                              void* d_out, int out_size)
{
    const float* x     = (const float*)d_in[0];
    const float* W_ih0 = (const float*)d_in[1];
    const float* W_hh0 = (const float*)d_in[2];
    const float* b_ih0 = (const float*)d_in[3];
    const float* b_hh0 = (const float*)d_in[4];
    const float* W_hr0 = (const float*)d_in[5];
    const float* W_ihs = (const float*)d_in[6];
    const float* W_hhs = (const float*)d_in[7];
    const float* b_ihs = (const float*)d_in[8];
    const float* b_hhs = (const float*)d_in[9];
    const float* W_hrs = (const float*)d_in[10];

    float *xg, *hpA, *hpB;
    __nv_bfloat16 *Abf, *Wbf, *Wgbf, *Wrbf;
    cudaGetSymbolAddress((void**)&xg,   g_xg);
    cudaGetSymbolAddress((void**)&hpA,  g_hpA);
    cudaGetSymbolAddress((void**)&hpB,  g_hpB);
    cudaGetSymbolAddress((void**)&Abf,  g_Abf);
    cudaGetSymbolAddress((void**)&Wbf,  g_Wbf);
    cudaGetSymbolAddress((void**)&Wgbf, g_Wgbf);
    cudaGetSymbolAddress((void**)&Wrbf, g_Wrbf);

    cudaFuncSetAttribute(lstm_scan_tc,
                         cudaFuncAttributeMaxDynamicSharedMemorySize, SCAN_SMEM);

    dim3 ggrid(32, 128);   // N/128, M/128

    // barrier reset (fresh every graph replay)
    reset_barrier_kernel<<<1, 256>>>();

    // scan weight conversions (all layers)
    conv_Whh_kernel<<<(G4H * PP) / 256, 256>>>(W_hh0, Wgbf);
    conv_Whr_kernel<<<(PP * HH) / 256, 256>>>(W_hr0, Wrbf);
    for (int l = 0; l < 3; l++) {
        conv_Whh_kernel<<<(G4H * PP) / 256, 256>>>(
            W_hhs + (size_t)l * G4H * PP, Wgbf + (size_t)(l + 1) * G4H * 768);
        conv_Whr_kernel<<<(PP * HH) / 256, 256>>>(
            W_hrs + (size_t)l * PP * HH, Wrbf + (size_t)(l + 1) * PP * 3072);
    }

    // ---- layer 0 ----
    conv_W_kernel<<<(G4H * DIN) / 256, 256>>>(W_ih0, Wbf, DIN);
    conv_A_kernel<<<(MROWS * DIN) / 256, 256>>>(x, Abf, DIN, 1);
    gemm_mma_kernel<<<ggrid, 256>>>(Abf, Wbf, b_ih0, b_hh0, xg, 3 * DIN);
    lstm_scan_tc<<<NBLK, 256, SCAN_SMEM>>>(xg, Wgbf, Wrbf, hpA, 0u);

    // ---- layers 1..3 ----
    float* cur = hpA;
    float* nxt = hpB;
    for (int l = 0; l < 3; l++) {
        conv_W_kernel<<<(G4H * PP) / 256, 256>>>(W_ihs + (size_t)l * G4H * PP, Wbf, PP);
        conv_A_kernel<<<(MROWS * PP) / 256, 256>>>(cur, Abf, PP, 0);
        gemm_mma_kernel<<<ggrid, 256>>>(Abf, Wbf,
                                        b_ihs + (size_t)l * G4H,
                                        b_hhs + (size_t)l * G4H,
                                        xg, 3 * PP);
        lstm_scan_tc<<<NBLK, 256, SCAN_SMEM>>>(xg,
                                               Wgbf + (size_t)(l + 1) * G4H * 768,
                                               Wrbf + (size_t)(l + 1) * PP * 3072,
                                               nxt, (unsigned)((l + 1) * 512));
        float* tmp = cur; cur = nxt; nxt = tmp;
    }

    // output = last timestep of final layer
    cudaMemcpyAsync(d_out, cur + (size_t)(TT - 1) * BB * PP,
                    (size_t)BB * PP * sizeof(float),
                    cudaMemcpyDeviceToDevice);
    (void)in_sizes; (void)n_in; (void)out_size;
}

// round 14
// speedup vs baseline: 1.5269x; 1.1456x over previous
#include <cuda_runtime.h>
#include <cuda_bf16.h>
#include <cstdint>

// Problem constants
#define BB   64      // batch
#define TT   256     // seq len
#define DIN  512     // input dim (layer 0)
#define HH   1024    // hidden
#define PP   256     // proj
#define G4H  4096    // 4*H
#define MROWS (TT*BB)  // 16384 GEMM rows
#define NBLK 128

// ---------------------------------------------------------------------------
// Scratch (__device__ globals; allocation is forbidden)
// ---------------------------------------------------------------------------
__device__ float g_xg[(size_t)MROWS * G4H];                 // [T*B, 4H] (unit-major permuted cols)
__device__ float g_hpA[(size_t)MROWS * PP];
__device__ float g_hpB[(size_t)MROWS * PP];
__device__ __align__(16) __nv_bfloat16 g_Abf[(size_t)MROWS * (3 * DIN)];
__device__ __align__(16) __nv_bfloat16 g_Wbf[(size_t)G4H * (3 * DIN)];
// scan tensor-core operands
__device__ __align__(16) __nv_bfloat16 g_Wgbf[4 * (size_t)G4H * 768];   // per-layer [4096][768] (unit-major rows)
__device__ __align__(16) __nv_bfloat16 g_Wrbf[4 * (size_t)PP * 3072];   // per-layer [256][3072]
__device__ __align__(16) __nv_bfloat16 g_hpbf[BB * 512];                // hp' [hi(256)|lo(256)]
__device__ __align__(16) __nv_bfloat16 g_hbf[BB * 2048];                // h'  [hi(1024)|lo(1024)]
__device__ float g_pp[4][BB][PP];                                       // proj split-K partials
// distributed barrier
__device__ unsigned g_flags[NBLK * 32];
__device__ unsigned g_rel;

// ---------------------------------------------------------------------------
// Helpers
// ---------------------------------------------------------------------------
__device__ __forceinline__ uint32_t smem_u32(const void* p) {
    uint32_t a;
    asm("{ .reg .u64 t; cvta.to.shared.u64 t, %1; cvt.u32.u64 %0, t; }" : "=r"(a) : "l"(p));
    return a;
}
__device__ __forceinline__ void cp_async16(uint32_t dst, const void* src) {
    asm volatile("cp.async.cg.shared.global [%0], [%1], 16;" :: "r"(dst), "l"(src));
}
__device__ __forceinline__ void cp_commit() {
    asm volatile("cp.async.commit_group;" ::: "memory");
}
template <int N>
__device__ __forceinline__ void cp_wait() {
    asm volatile("cp.async.wait_group %0;" :: "n"(N) : "memory");
}
__device__ __forceinline__ void ldm_x4(uint32_t addr, uint32_t& r0, uint32_t& r1,
                                       uint32_t& r2, uint32_t& r3) {
    asm volatile("ldmatrix.sync.aligned.m8n8.x4.shared.b16 {%0,%1,%2,%3}, [%4];"
                 : "=r"(r0), "=r"(r1), "=r"(r2), "=r"(r3) : "r"(addr));
}
__device__ __forceinline__ void ldm_x2(uint32_t addr, uint32_t& r0, uint32_t& r1) {
    asm volatile("ldmatrix.sync.aligned.m8n8.x2.shared.b16 {%0,%1}, [%2];"
                 : "=r"(r0), "=r"(r1) : "r"(addr));
}
__device__ __forceinline__ void mma16816(float* d, const uint32_t* a,
                                         uint32_t b0, uint32_t b1) {
    asm volatile(
        "mma.sync.aligned.m16n8k16.row.col.f32.bf16.bf16.f32 "
        "{%0,%1,%2,%3}, {%4,%5,%6,%7}, {%8,%9}, {%0,%1,%2,%3};"
        : "+f"(d[0]), "+f"(d[1]), "+f"(d[2]), "+f"(d[3])
        : "r"(a[0]), "r"(a[1]), "r"(a[2]), "r"(a[3]), "r"(b0), "r"(b1));
}

// ---------------------------------------------------------------------------
// Distributed grid barrier: per-block flag (monotone counter), block 0 releases.
// ---------------------------------------------------------------------------
__device__ __forceinline__ void bar_sync(int j, unsigned p) {
    __syncthreads();
    __threadfence();
    if (threadIdx.x == 0)
        ((volatile unsigned*)g_flags)[j * 32] = p;
    if (j == 0) {
        if (threadIdx.x < NBLK) {
            volatile unsigned* f = ((volatile unsigned*)g_flags) + threadIdx.x * 32;
            while (*f < p) { }
        }
        __syncthreads();
        __threadfence();
        if (threadIdx.x == 0) *(volatile unsigned*)&g_rel = p;
        __syncthreads();
    } else {
        if (threadIdx.x == 0) {
            while (*(volatile unsigned*)&g_rel < p) { }
        }
        __syncthreads();
        __threadfence();
    }
}

__global__ void reset_barrier_kernel() {
    int i = threadIdx.x;
    if (i < NBLK) g_flags[i * 32] = 0;
    if (i == 0) g_rel = 0;
}

// ---------------------------------------------------------------------------
// fp32 -> split bf16 conversions for the input GEMM.
// A': [hi|hi|lo], W': [hi|lo|hi]. W rows permuted to unit-major.
// ---------------------------------------------------------------------------
__global__ void conv_A_kernel(const float* __restrict__ in, __nv_bfloat16* __restrict__ out,
                              int K, int remap) {
    int idx = blockIdx.x * 256 + threadIdx.x;
    if (idx >= MROWS * K) return;
    int m = idx / K;
    int k = idx - m * K;
    float a = in[idx];
    int r = remap ? (((m & 255) << 6) | (m >> 8)) : m;   // (b,t) -> row t*64+b
    __nv_bfloat16 hi = __float2bfloat16(a);
    __nv_bfloat16 lo = __float2bfloat16(a - __bfloat162float(hi));
    size_t base = (size_t)r * (3 * K);
    out[base + k] = hi;
    out[base + K + k] = hi;
    out[base + 2 * K + k] = lo;
}

__global__ void conv_W_kernel(const float* __restrict__ in, __nv_bfloat16* __restrict__ out,
                              int K) {
    int idx = blockIdx.x * 256 + threadIdx.x;
    if (idx >= G4H * K) return;
    int n = idx / K;
    int k = idx - n * K;
    float a = in[idx];
    __nv_bfloat16 hi = __float2bfloat16(a);
    __nv_bfloat16 lo = __float2bfloat16(a - __bfloat162float(hi));
    int np = 4 * (n & 1023) + (n >> 10);     // gate-major -> unit-major row permutation
    size_t base = (size_t)np * (3 * K);
    out[base + k] = hi;
    out[base + K + k] = lo;
    out[base + 2 * K + k] = hi;
}

// Scan weight conversions
__global__ void conv_Whh_kernel(const float* __restrict__ in, __nv_bfloat16* __restrict__ out) {
    int idx = blockIdx.x * 256 + threadIdx.x;    // over 4096*256
    if (idx >= G4H * PP) return;
    int n = idx >> 8, k = idx & 255;
    float a = in[idx];
    __nv_bfloat16 hi = __float2bfloat16(a);
    __nv_bfloat16 lo = __float2bfloat16(a - __bfloat162float(hi));
    int np = 4 * (n & 1023) + (n >> 10);
    size_t base = (size_t)np * 768;
    out[base + k] = hi;          // [Whi | Wlo | Whi]
    out[base + 256 + k] = lo;
    out[base + 512 + k] = hi;
}
__global__ void conv_Whr_kernel(const float* __restrict__ in, __nv_bfloat16* __restrict__ out) {
    int idx = blockIdx.x * 256 + threadIdx.x;    // over 256*1024
    if (idx >= PP * HH) return;
    int n = idx >> 10, k = idx & 1023;
    float a = in[idx];
    __nv_bfloat16 hi = __float2bfloat16(a);
    __nv_bfloat16 lo = __float2bfloat16(a - __bfloat162float(hi));
    size_t base = (size_t)n * 3072;
    out[base + k] = hi;          // [Whi | Wlo | Whi]
    out[base + 1024 + k] = lo;
    out[base + 2048 + k] = hi;
}

// ---------------------------------------------------------------------------
// Input-projection GEMM via mma.sync (unchanged, passing since R9/R11).
// ---------------------------------------------------------------------------
#define LDS_ROW 40
#define TILE_BYTES (128 * LDS_ROW * 2)

__global__ __launch_bounds__(256) void gemm_mma_kernel(
    const __nv_bfloat16* __restrict__ A,
    const __nv_bfloat16* __restrict__ W,
    const float* __restrict__ b1, const float* __restrict__ b2,
    float* __restrict__ C, int K3)
{
    __shared__ alignas(16) __nv_bfloat16 sA[2][128][LDS_ROW];
    __shared__ alignas(16) __nv_bfloat16 sB[2][128][LDS_ROW];

    const int tid  = threadIdx.x;
    const int wid  = tid >> 5;
    const int lane = tid & 31;
    const int m0 = blockIdx.y * 128;
    const int n0 = blockIdx.x * 128;
    const int wm = (wid >> 2) * 64;
    const int wn = (wid & 3) * 32;

    const uint32_t sA_u = smem_u32(sA);
    const uint32_t sB_u = smem_u32(sB);

    float acc[4][4][4];
#pragma unroll
    for (int mi = 0; mi < 4; mi++)
#pragma unroll
        for (int nj = 0; nj < 4; nj++)
#pragma unroll
            for (int e = 0; e < 4; e++) acc[mi][nj][e] = 0.f;

    const int nchunks = K3 >> 5;

    const uint32_t a_off = (uint32_t)((wm + (lane & 15)) * LDS_ROW + ((lane >> 4) * 8)) * 2;
    const uint32_t b_off = (uint32_t)((wn + ((lane >> 3) & 1) * 8 + (lane & 7)) * LDS_ROW
                                      + ((lane >> 4) * 8)) * 2;

    {
        const __nv_bfloat16* Ag = A + (size_t)m0 * K3;
        const __nv_bfloat16* Wg = W + (size_t)n0 * K3;
#pragma unroll
        for (int i = 0; i < 2; i++) {
            int seg = i * 256 + tid;
            int row = seg >> 2, s = seg & 3;
            uint32_t off = (uint32_t)(row * LDS_ROW + s * 8) * 2;
            cp_async16(sA_u + off, Ag + (size_t)row * K3 + s * 8);
            cp_async16(sB_u + off, Wg + (size_t)row * K3 + s * 8);
        }
        cp_commit();
    }

    for (int c = 0; c < nchunks; c++) {
        const int buf = c & 1;
        if (c + 1 < nchunks) {
            const int nb = (c + 1) & 1;
            const __nv_bfloat16* Ag = A + (size_t)m0 * K3 + (c + 1) * 32;
            const __nv_bfloat16* Wg = W + (size_t)n0 * K3 + (c + 1) * 32;
#pragma unroll
            for (int i = 0; i < 2; i++) {
                int seg = i * 256 + tid;
                int row = seg >> 2, s = seg & 3;
                uint32_t off = (uint32_t)(nb * TILE_BYTES + (row * LDS_ROW + s * 8) * 2);
                cp_async16(sA_u + off, Ag + (size_t)row * K3 + s * 8);
                cp_async16(sB_u + off, Wg + (size_t)row * K3 + s * 8);
            }
            cp_commit();
            cp_wait<1>();
        } else {
            cp_wait<0>();
        }
        __syncthreads();

        const uint32_t abase = sA_u + buf * TILE_BYTES;
        const uint32_t bbase = sB_u + buf * TILE_BYTES;
#pragma unroll
        for (int ks = 0; ks < 2; ks++) {
            const uint32_t koff = (uint32_t)(ks * 16 * 2);
            uint32_t a[4][4];
#pragma unroll
            for (int mi = 0; mi < 4; mi++)
                ldm_x4(abase + a_off + koff + (uint32_t)(mi * 16 * LDS_ROW * 2),
                       a[mi][0], a[mi][1], a[mi][2], a[mi][3]);
            uint32_t bfrag[4][2];
#pragma unroll
            for (int g = 0; g < 2; g++) {
                uint32_t r0, r1, r2, r3;
                ldm_x4(bbase + b_off + koff + (uint32_t)(g * 16 * LDS_ROW * 2),
                       r0, r1, r2, r3);
                bfrag[g * 2 + 0][0] = r0; bfrag[g * 2 + 0][1] = r2;
                bfrag[g * 2 + 1][0] = r1; bfrag[g * 2 + 1][1] = r3;
            }
#pragma unroll
            for (int mi = 0; mi < 4; mi++)
#pragma unroll
                for (int nj = 0; nj < 4; nj++)
                    mma16816(acc[mi][nj], a[mi], bfrag[nj][0], bfrag[nj][1]);
        }
        __syncthreads();
    }

    // Epilogue: bias with inverse permutation (col n' -> orig (n'&3)*1024 + n'>>2)
    float bs0[4], bs1[4];
#pragma unroll
    for (int nj = 0; nj < 4; nj++) {
        int n = n0 + wn + nj * 8 + (lane & 3) * 2;
        int o0 = ((n & 3) << 10) | (n >> 2);
        int o1 = (((n + 1) & 3) << 10) | ((n + 1) >> 2);
        bs0[nj] = b1[o0] + b2[o0];
        bs1[nj] = b1[o1] + b2[o1];
    }
#pragma unroll
    for (int mi = 0; mi < 4; mi++) {
        int mrow = m0 + wm + mi * 16 + (lane >> 2);
#pragma unroll
        for (int nj = 0; nj < 4; nj++) {
            int n = n0 + wn + nj * 8 + (lane & 3) * 2;
            float2 v0 = make_float2(acc[mi][nj][0] + bs0[nj], acc[mi][nj][1] + bs1[nj]);
            float2 v1 = make_float2(acc[mi][nj][2] + bs0[nj], acc[mi][nj][3] + bs1[nj]);
            *(float2*)&C[(size_t)mrow * G4H + n]       = v0;
            *(float2*)&C[(size_t)(mrow + 8) * G4H + n] = v1;
        }
    }
}

// ---------------------------------------------------------------------------
// Tensor-core persistent LSTM scan, v3.
// 128 blocks x 256 threads. Per step:
//   gate: 4 unique A-chunks (hp' [hi|lo], 64KB), 6 mma passes, slot map
//         {0,1,0,1,2,3} vs Wg'=[hi|lo|hi].
//   cell: local (lane-pair shuffle), h' -> global [hi|lo].
//   bar1; proj split-K4: block j => N-group g=j&31 (8 cols), K-quarter
//         q=j>>5 (aligned to hi/lo structure: 4 unique chunks, 6 passes);
//         partials -> g_pp. bar2; reduce (128 outputs/block) -> hp fp32 +
//         hp' [hi|lo]. bar3.
//   xg(t+1) prefetched during proj into double-buffered SMEM tile.
// ---------------------------------------------------------------------------
#define CH_ROW   136
#define CH_BYTES (64 * CH_ROW * 2)     // 17408

#define OFF_WG 0
#define SZ_WG  (32 * 776 * 2)          // 49664
#define OFF_WR (OFF_WG + SZ_WG)
#define SZ_WR  (8 * 3080 * 2)          // 49280
#define OFF_ST (OFF_WR + SZ_WR)
#define SZ_ST  (4 * CH_BYTES)          // 69632
#define OFF_SH (OFF_ST + SZ_ST)
#define SZ_SH  (64 * 9 * 4)            // 2304
#define OFF_XG (OFF_SH + SZ_SH)
#define SZ_XG  (2 * 64 * 36 * 4)       // 18432 (double-buffered)
#define SCAN_SMEM (OFF_XG + SZ_XG)     // 189312

__global__ __launch_bounds__(256, 1) void lstm_scan_tc(
    const float* __restrict__ xg,
    const __nv_bfloat16* __restrict__ Wg,
    const __nv_bfloat16* __restrict__ Wr,
    float* __restrict__ hp_out,
    unsigned pbase)
{
    extern __shared__ char dsm[];
    float* sH = (float*)(dsm + OFF_SH);
    float* sXg = (float*)(dsm + OFF_XG);
    const uint32_t sWg_u = smem_u32(dsm + OFF_WG);
    const uint32_t sWr_u = smem_u32(dsm + OFF_WR);
    const uint32_t st_u  = smem_u32(dsm + OFF_ST);
    const uint32_t sXg_u = smem_u32(dsm + OFF_XG);

    const int tid = threadIdx.x;
    const int lane = tid & 31;
    const int w = tid >> 5;
    const int j = blockIdx.x;
    const int g = j & 31;          // proj N-group (8 cols)
    const int q = j >> 5;          // proj K-quarter
    const int wq = q * 256;
    const int wm = (w & 3) * 16;
    const int wn = (w >> 2) * 16;

    // ---- load persistent weight slices + xg(0) ----
    for (int i = tid; i < 3072; i += 256) {            // Wg: 32 rows x 96 segs
        int r = i / 96, s = i % 96;
        cp_async16(sWg_u + (uint32_t)(r * 776 + s * 8) * 2,
                   Wg + (size_t)(j * 32 + r) * 768 + s * 8);
    }
    for (int i = tid; i < 3072; i += 256) {            // Wr: 8 rows x 384 segs
        int r = i / 384, s = i % 384;
        cp_async16(sWr_u + (uint32_t)(r * 3080 + s * 8) * 2,
                   Wr + (size_t)(g * 8 + r) * 3072 + s * 8);
    }
    for (int k = 0; k < 2; k++) {                       // xg(0) -> buffer 0
        int i = k * 256 + tid;
        int r = i >> 3, s = i & 7;
        cp_async16(sXg_u + (uint32_t)(r * 144 + s * 16),
                   xg + (size_t)r * G4H + j * 32 + s * 4);
    }
    cp_commit();
    cp_wait<0>();
    __syncthreads();

    float cst[4] = {0.f, 0.f, 0.f, 0.f};   // cell state (even lanes): [nj*2+rp]

    for (int t = 0; t < TT; t++) {
        float acc[2][4];
#pragma unroll
        for (int nj = 0; nj < 2; nj++)
#pragma unroll
            for (int e = 0; e < 4; e++) acc[nj][e] = 0.f;

        // ================= gate phase =================
        if (t > 0) {
            // 4 unique A-chunks from hp' [64][512]
#pragma unroll
            for (int a = 0; a < 4; a++) {
#pragma unroll
                for (int k = 0; k < 4; k++) {
                    int i = k * 256 + tid;
                    int r = i >> 4, s = i & 15;
                    cp_async16(st_u + (uint32_t)(a * CH_BYTES + (r * CH_ROW + s * 8) * 2),
                               g_hpbf + (size_t)r * 512 + a * 128 + s * 8);
                }
                cp_commit();
            }
#pragma unroll
            for (int p = 0; p < 6; p++) {
                if (p == 0)      { cp_wait<3>(); __syncthreads(); }
                else if (p == 1) { cp_wait<2>(); __syncthreads(); }
                else if (p == 4) { cp_wait<0>(); __syncthreads(); }
                const int sl = (p < 4) ? (p & 1) : (p - 2);
                const uint32_t abase = st_u + (uint32_t)(sl * CH_BYTES);
                const int wb = p * 128;
#pragma unroll
                for (int ks = 0; ks < 8; ks++) {
                    uint32_t a[4], r0, r1, r2, r3;
                    ldm_x4(abase + (uint32_t)((wm + (lane & 15)) * CH_ROW
                                              + (lane >> 4) * 8 + ks * 16) * 2,
                           a[0], a[1], a[2], a[3]);
                    ldm_x4(sWg_u + (uint32_t)((wn + ((lane >> 3) & 1) * 8 + (lane & 7)) * 776
                                              + (lane >> 4) * 8 + wb + ks * 16) * 2,
                           r0, r1, r2, r3);
                    mma16816(acc[0], a, r0, r2);
                    mma16816(acc[1], a, r1, r3);
                }
            }
        }

        // ---- add xg (SMEM, buffer t&1), cell update ----
        {
            const float* sx = sXg + (t & 1) * (64 * 36);
            int rbase = wm + (lane >> 2);
#pragma unroll
            for (int nj = 0; nj < 2; nj++) {
#pragma unroll
                for (int rp = 0; rp < 2; rp++) {
                    int row = rbase + rp * 8;
                    int cl = wn + nj * 8 + (lane & 3) * 2;
                    float2 xv = *(const float2*)&sx[row * 36 + cl];
                    float x0 = acc[nj][rp * 2 + 0] + xv.x;
                    float x1 = acc[nj][rp * 2 + 1] + xv.y;
                    float y0 = __shfl_xor_sync(0xffffffffu, x0, 1);
                    float y1 = __shfl_xor_sync(0xffffffffu, x1, 1);
                    if (!(lane & 1)) {
                        float gi = 1.f / (1.f + __expf(-x0));
                        float gf = 1.f / (1.f + __expf(-x1));
                        float gg = tanhf(y0);
                        float go = 1.f / (1.f + __expf(-y1));
                        float c = gf * cst[nj * 2 + rp] + gi * gg;
                        cst[nj * 2 + rp] = c;
                        float h = go * tanhf(c);
                        sH[row * 9 + (cl >> 2)] = h;
                    }
                }
            }
        }
        __syncthreads();

        // ---- h' writeback: [hi|lo], units j*8..+8 ----
        if (tid < 64) {
            __align__(16) __nv_bfloat16 hi8[8], lo8[8];
#pragma unroll
            for (int u = 0; u < 8; u++) {
                float hv = sH[tid * 9 + u];
                hi8[u] = __float2bfloat16(hv);
                lo8[u] = __float2bfloat16(hv - __bfloat162float(hi8[u]));
            }
            __nv_bfloat16* dst = g_hbf + (size_t)tid * 2048 + j * 8;
            __stcg((uint4*)dst,          *(const uint4*)hi8);
            __stcg((uint4*)(dst + 1024), *(const uint4*)lo8);
        }

        bar_sync(j, pbase + 3 * t + 1);

        // ================= projection phase (split-K4) =================
        {
            // bundle xg(t+1) with chunk 0
            if (t + 1 < TT) {
#pragma unroll
                for (int k = 0; k < 2; k++) {
                    int i = k * 256 + tid;
                    int r = i >> 3, s = i & 7;
                    cp_async16(sXg_u + (uint32_t)(((t + 1) & 1) * (64 * 144) + r * 144 + s * 16),
                               xg + (size_t)((t + 1) * 64 + r) * G4H + j * 32 + s * 4);
                }
            }
            const int cb[4] = {wq, wq + 128, 1024 + wq, 1024 + wq + 128};
#pragma unroll
            for (int a = 0; a < 4; a++) {
#pragma unroll
                for (int k = 0; k < 4; k++) {
                    int i = k * 256 + tid;
                    int r = i >> 4, s = i & 15;
                    cp_async16(st_u + (uint32_t)(a * CH_BYTES + (r * CH_ROW + s * 8) * 2),
                               g_hbf + (size_t)r * 2048 + cb[a] + s * 8);
                }
                cp_commit();
            }

            float accP[4] = {0.f, 0.f, 0.f, 0.f};
            const int wb[6] = {wq, wq + 128, 1024 + wq, 1024 + wq + 128,
                               2048 + wq, 2048 + wq + 128};
#pragma unroll
            for (int p = 0; p < 6; p++) {
                if (p == 0)      { cp_wait<3>(); __syncthreads(); }
                else if (p == 1) { cp_wait<2>(); __syncthreads(); }
                else if (p == 4) { cp_wait<0>(); __syncthreads(); }
                if (w < 4) {
                    const int sl = (p < 4) ? (p & 1) : (p - 2);
                    const uint32_t abase = st_u + (uint32_t)(sl * CH_BYTES);
#pragma unroll
                    for (int ks = 0; ks < 8; ks++) {
                        uint32_t a[4], b0, b1;
                        ldm_x4(abase + (uint32_t)((w * 16 + (lane & 15)) * CH_ROW
                                                  + (lane >> 4) * 8 + ks * 16) * 2,
                               a[0], a[1], a[2], a[3]);
                        ldm_x2(sWr_u + (uint32_t)((lane & 7) * 3080 + ((lane >> 3) & 1) * 8
                                                  + wb[p] + ks * 16) * 2,
                               b0, b1);
                        mma16816(accP, a, b0, b1);
                    }
                }
            }
            // write partials to g_pp[q]
            if (w < 4) {
                int row = w * 16 + (lane >> 2);
                int col = g * 8 + (lane & 3) * 2;
                float* pp = &g_pp[q][0][0];
                *(float2*)&pp[row * 256 + col]       = make_float2(accP[0], accP[1]);
                *(float2*)&pp[(row + 8) * 256 + col] = make_float2(accP[2], accP[3]);
            }
        }

        bar_sync(j, pbase + 3 * t + 2);

        // ================= reduce phase =================
        if (tid < 128) {
            int r = j >> 1;
            int c = (j & 1) * 128 + tid;
            float s = __ldcg(&g_pp[0][r][c]) + __ldcg(&g_pp[1][r][c])
                    + __ldcg(&g_pp[2][r][c]) + __ldcg(&g_pp[3][r][c]);
            hp_out[((size_t)t * 64 + r) * PP + c] = s;
            __nv_bfloat16 hi = __float2bfloat16(s);
            __nv_bfloat16 lo = __float2bfloat16(s - __bfloat162float(hi));
            g_hpbf[r * 512 + c]       = hi;
            g_hpbf[r * 512 + 256 + c] = lo;
        }

        bar_sync(j, pbase + 3 * t + 3);
    }
}

// ---------------------------------------------------------------------------
// Launch
// ---------------------------------------------------------------------------
extern "C" void kernel_launch(void* const* d_in, const int* in_sizes, int n_in,
                              void* d_out, int out_size)
{
    const float* x     = (const float*)d_in[0];
    const float* W_ih0 = (const float*)d_in[1];
    const float* W_hh0 = (const float*)d_in[2];
    const float* b_ih0 = (const float*)d_in[3];
    const float* b_hh0 = (const float*)d_in[4];
    const float* W_hr0 = (const float*)d_in[5];
    const float* W_ihs = (const float*)d_in[6];
    const float* W_hhs = (const float*)d_in[7];
    const float* b_ihs = (const float*)d_in[8];
    const float* b_hhs = (const float*)d_in[9];
    const float* W_hrs = (const float*)d_in[10];

    float *xg, *hpA, *hpB;
    __nv_bfloat16 *Abf, *Wbf, *Wgbf, *Wrbf;
    cudaGetSymbolAddress((void**)&xg,   g_xg);
    cudaGetSymbolAddress((void**)&hpA,  g_hpA);
    cudaGetSymbolAddress((void**)&hpB,  g_hpB);
    cudaGetSymbolAddress((void**)&Abf,  g_Abf);
    cudaGetSymbolAddress((void**)&Wbf,  g_Wbf);
    cudaGetSymbolAddress((void**)&Wgbf, g_Wgbf);
    cudaGetSymbolAddress((void**)&Wrbf, g_Wrbf);

    cudaFuncSetAttribute(lstm_scan_tc,
                         cudaFuncAttributeMaxDynamicSharedMemorySize, SCAN_SMEM);

    dim3 ggrid(32, 128);   // N/128, M/128

    // barrier reset (fresh every graph replay)
    reset_barrier_kernel<<<1, 256>>>();

    // scan weight conversions (all layers)
    conv_Whh_kernel<<<(G4H * PP) / 256, 256>>>(W_hh0, Wgbf);
    conv_Whr_kernel<<<(PP * HH) / 256, 256>>>(W_hr0, Wrbf);
    for (int l = 0; l < 3; l++) {
        conv_Whh_kernel<<<(G4H * PP) / 256, 256>>>(
            W_hhs + (size_t)l * G4H * PP, Wgbf + (size_t)(l + 1) * G4H * 768);
        conv_Whr_kernel<<<(PP * HH) / 256, 256>>>(
            W_hrs + (size_t)l * PP * HH, Wrbf + (size_t)(l + 1) * PP * 3072);
    }

    // ---- layer 0 ----
    conv_W_kernel<<<(G4H * DIN) / 256, 256>>>(W_ih0, Wbf, DIN);
    conv_A_kernel<<<(MROWS * DIN) / 256, 256>>>(x, Abf, DIN, 1);
    gemm_mma_kernel<<<ggrid, 256>>>(Abf, Wbf, b_ih0, b_hh0, xg, 3 * DIN);
    lstm_scan_tc<<<NBLK, 256, SCAN_SMEM>>>(xg, Wgbf, Wrbf, hpA, 0u);

    // ---- layers 1..3 ----
    float* cur = hpA;
    float* nxt = hpB;
    for (int l = 0; l < 3; l++) {
        conv_W_kernel<<<(G4H * PP) / 256, 256>>>(W_ihs + (size_t)l * G4H * PP, Wbf, PP);
        conv_A_kernel<<<(MROWS * PP) / 256, 256>>>(cur, Abf, PP, 0);
        gemm_mma_kernel<<<ggrid, 256>>>(Abf, Wbf,
                                        b_ihs + (size_t)l * G4H,
                                        b_hhs + (size_t)l * G4H,
                                        xg, 3 * PP);
        lstm_scan_tc<<<NBLK, 256, SCAN_SMEM>>>(xg,
                                               Wgbf + (size_t)(l + 1) * G4H * 768,
                                               Wrbf + (size_t)(l + 1) * PP * 3072,
                                               nxt, (unsigned)((l + 1) * 3 * TT));
        float* tmp = cur; cur = nxt; nxt = tmp;
    }

    // output = last timestep of final layer
    cudaMemcpyAsync(d_out, cur + (size_t)(TT - 1) * BB * PP,
                    (size_t)BB * PP * sizeof(float),
                    cudaMemcpyDeviceToDevice);
    (void)in_sizes; (void)n_in; (void)out_size;
}